// round 1
// baseline (speedup 1.0000x reference)
#include <cuda_runtime.h>
#include <cstdint>

#define H   8
#define Dd  32
#define HD  256
#define NC  10000
#define NS  1024
#define INC 128
#define INS 64
#define ECC 120000
#define ECS 10000
#define LALPHA 0.2f
#define NEG_BIG -1e30f

// ---------------- device scratch (static; no runtime allocation) ----------------
__device__ float g_Wh_cc[9u * NC * HD];     // 92.2 MB
__device__ float g_Wh_cs[3u * NC * HD];     // 30.7 MB
__device__ float g_Wh_in[NS * HD];

__device__ float g_as_cc[9 * NC * H];
__device__ float g_ad_cc[9 * NC * H];
__device__ float g_as_cs[3 * NC * H];

__device__ float g_wred_as[9 * INC * H];
__device__ float g_wred_ad[9 * INC * H];
__device__ float g_wred_as_cs[3 * INC * H];
__device__ float g_bred_as[9 * H];
__device__ float g_bred_ad[9 * H];
__device__ float g_bred_as_cs[3 * H];

__device__ int g_cnt_cc[9 * NC];
__device__ int g_off_cc[9 * NC];
__device__ int g_cur_cc[9 * NC];
__device__ int g_csr_cc[9 * ECC];
__device__ int g_cnt_cs[3 * NS];
__device__ int g_off_cs[3 * NS];
__device__ int g_cur_cs[3 * NS];
__device__ int g_csr_cs[3 * ECS];

// ---------------- zero counters ----------------
__global__ void k_zero_counters() {
    int i = blockIdx.x * blockDim.x + threadIdx.x;
    if (i < 9 * NC) g_cnt_cc[i] = 0;
    if (i < 3 * NS) g_cnt_cs[i] = 0;
}

// ---------------- reduce attention vectors into weights ----------------
// a = (feat @ W + b) . attn  ==  feat @ (W . attn) + (b . attn)
__global__ void k_wred(const float* __restrict__ W_node, const float* __restrict__ b_node,
                       const float* __restrict__ W_cc,   const float* __restrict__ b_cc,
                       const float* __restrict__ W_cs,   const float* __restrict__ b_cs,
                       const float* __restrict__ attn_cc, const float* __restrict__ attn_cs) {
    int gid = blockIdx.x * blockDim.x + threadIdx.x;
    if (gid >= 21 * INC * H) return;
    int j   = gid / (INC * H);
    int rem = gid % (INC * H);
    int k = rem / H, h = rem % H;
    const float *Wsrc, *att, *bvec;
    float *dst, *bdst;
    if (j < 9) {                       // a_src for cc relation j (uses W_cc[j], attn_cc[j][0])
        Wsrc = W_cc + (size_t)j * INC * HD;
        att  = attn_cc + (size_t)(j * 2 + 0) * HD;
        bvec = b_cc + (size_t)j * HD;
        dst  = g_wred_as + j * INC * H; bdst = g_bred_as + j * H;
    } else if (j < 18) {               // a_dst for cc relation r (uses W_node[r%3], attn_cc[r][1])
        int r = j - 9;
        Wsrc = W_node + (size_t)(r % 3) * INC * HD;
        att  = attn_cc + (size_t)(r * 2 + 1) * HD;
        bvec = b_node + (size_t)(r % 3) * HD;
        dst  = g_wred_ad + r * INC * H; bdst = g_bred_ad + r * H;
    } else {                           // a_src for cs relation t (uses W_cs[t], attn_cs[t][0])
        int t = j - 18;
        Wsrc = W_cs + (size_t)t * INC * HD;
        att  = attn_cs + (size_t)(t * 2 + 0) * HD;
        bvec = b_cs + (size_t)t * HD;
        dst  = g_wred_as_cs + t * INC * H; bdst = g_bred_as_cs + t * H;
    }
    float s = 0.f;
    #pragma unroll
    for (int d = 0; d < Dd; d++)
        s += Wsrc[(size_t)k * HD + h * Dd + d] * att[h * Dd + d];
    dst[k * H + h] = s;
    if (k == 0) {
        float bs = 0.f;
        #pragma unroll
        for (int d = 0; d < Dd; d++) bs += bvec[h * Dd + d] * att[h * Dd + d];
        bdst[h] = bs;
    }
}

// ---------------- skinny GEMMs: [10000,128] @ [128,8] -> per-node attn scalars --------
__global__ void __launch_bounds__(256) k_skinny(const float* __restrict__ f1,
                                                const float* __restrict__ f2,
                                                const float* __restrict__ f3) {
    int y = blockIdx.y;
    const float* feat; const float* wred; const float* bred; float* outp;
    {
        int sel;
        if (y < 9)       { sel = y / 3;        wred = g_wred_as + y * INC * H;          bred = g_bred_as + y * H;          outp = g_as_cc + (size_t)y * NC * H; }
        else if (y < 18) { int r = y - 9; sel = r % 3; wred = g_wred_ad + r * INC * H;  bred = g_bred_ad + r * H;          outp = g_ad_cc + (size_t)r * NC * H; }
        else             { int t = y - 18; sel = t;    wred = g_wred_as_cs + t * INC * H; bred = g_bred_as_cs + t * H;     outp = g_as_cs + (size_t)t * NC * H; }
        feat = (sel == 0) ? f1 : (sel == 1) ? f2 : f3;
    }
    __shared__ float Wst[H * INC];   // transposed: [h][k]
    __shared__ float bs[H];
    for (int idx = threadIdx.x; idx < INC * H; idx += 256) {
        int h = idx / INC, k = idx % INC;
        Wst[idx] = wred[k * H + h];
    }
    if (threadIdx.x < H) bs[threadIdx.x] = bred[threadIdx.x];
    __syncthreads();

    int warp = threadIdx.x / 32, lane = threadIdx.x % 32;
    int node = blockIdx.x * 8 + warp;
    if (node >= NC) return;
    const float* frow = feat + (size_t)node * INC;
    float p[H] = {};
    #pragma unroll
    for (int c = 0; c < 4; c++) {
        int k = c * 32 + lane;
        float f = frow[k];
        #pragma unroll
        for (int h = 0; h < H; h++) p[h] += f * Wst[h * INC + k];
    }
    float mine = 0.f;
    #pragma unroll
    for (int h = 0; h < H; h++) {
        float v = p[h];
        #pragma unroll
        for (int o = 16; o > 0; o >>= 1) v += __shfl_xor_sync(0xffffffffu, v, o);
        if (lane == h) mine = v;
    }
    if (lane < H) outp[(size_t)node * H + lane] = mine + bs[lane];
}

// ---------------- big GEMMs: 13 jobs of [M,K] @ [K,256] + bias -------------------
__global__ void __launch_bounds__(256) k_gemm(const float* __restrict__ f1, const float* __restrict__ f2,
                                              const float* __restrict__ f3, const float* __restrict__ fs,
                                              const float* __restrict__ Wcc, const float* __restrict__ bcc,
                                              const float* __restrict__ Wcs, const float* __restrict__ bcs,
                                              const float* __restrict__ Win, const float* __restrict__ bin) {
    int z = blockIdx.z;
    const float* A; const float* W; const float* bptr; float* outp; int M, K;
    if (z < 9) {
        int s = z / 3;
        A = (s == 0) ? f1 : (s == 1) ? f2 : f3;
        W = Wcc + (size_t)z * INC * HD; bptr = bcc + (size_t)z * HD;
        outp = g_Wh_cc + (size_t)z * NC * HD; M = NC; K = INC;
    } else if (z < 12) {
        int t = z - 9;
        A = (t == 0) ? f1 : (t == 1) ? f2 : f3;
        W = Wcs + (size_t)t * INC * HD; bptr = bcs + (size_t)t * HD;
        outp = g_Wh_cs + (size_t)t * NC * HD; M = NC; K = INC;
    } else {
        A = fs; W = Win; bptr = bin; outp = g_Wh_in; M = NS; K = INS;
    }
    int row0 = blockIdx.x * 128;
    if (row0 >= M) return;
    int col0 = blockIdx.y * 128;

    __shared__ float As[16][128];
    __shared__ float Bs[16][128];
    int tid = threadIdx.x;
    int tx = tid % 16, ty = tid / 16;
    float acc[8][8] = {};

    for (int kt = 0; kt < K; kt += 16) {
        #pragma unroll
        for (int i = 0; i < 2; i++) {
            int idx = tid * 2 + i;           // 0..511
            int r = idx >> 2;                // 0..127
            int c4 = (idx & 3) * 4;          // 0,4,8,12
            float4 v = make_float4(0.f, 0.f, 0.f, 0.f);
            if (row0 + r < M)
                v = *(const float4*)(A + (size_t)(row0 + r) * K + kt + c4);
            As[c4 + 0][r] = v.x; As[c4 + 1][r] = v.y; As[c4 + 2][r] = v.z; As[c4 + 3][r] = v.w;
        }
        #pragma unroll
        for (int i = 0; i < 2; i++) {
            int idx = tid * 2 + i;
            int r = idx >> 5;                // 0..15
            int c4 = (idx & 31) * 4;         // 0..124
            float4 v = *(const float4*)(W + (size_t)(kt + r) * HD + col0 + c4);
            *(float4*)&Bs[r][c4] = v;
        }
        __syncthreads();
        #pragma unroll
        for (int k = 0; k < 16; k++) {
            float a[8], b[8];
            *(float4*)&a[0] = *(const float4*)&As[k][ty * 8];
            *(float4*)&a[4] = *(const float4*)&As[k][ty * 8 + 4];
            *(float4*)&b[0] = *(const float4*)&Bs[k][tx * 8];
            *(float4*)&b[4] = *(const float4*)&Bs[k][tx * 8 + 4];
            #pragma unroll
            for (int i = 0; i < 8; i++)
                #pragma unroll
                for (int j = 0; j < 8; j++)
                    acc[i][j] += a[i] * b[j];
        }
        __syncthreads();
    }
    float bb[8];
    #pragma unroll
    for (int j = 0; j < 8; j++) bb[j] = bptr[col0 + tx * 8 + j];
    #pragma unroll
    for (int i = 0; i < 8; i++) {
        int r = row0 + ty * 8 + i;
        if (r < M) {
            float* orow = outp + (size_t)r * HD + col0 + tx * 8;
            float4 v0, v1;
            v0.x = acc[i][0] + bb[0]; v0.y = acc[i][1] + bb[1];
            v0.z = acc[i][2] + bb[2]; v0.w = acc[i][3] + bb[3];
            v1.x = acc[i][4] + bb[4]; v1.y = acc[i][5] + bb[5];
            v1.z = acc[i][6] + bb[6]; v1.w = acc[i][7] + bb[7];
            *(float4*)(orow)     = v0;
            *(float4*)(orow + 4) = v1;
        }
    }
}

// ---------------- CSR build: histogram, scan, scatter ----------------
__global__ void k_hist(const int* __restrict__ ecc_dst, const int* __restrict__ ecs_dst) {
    int gid = blockIdx.x * blockDim.x + threadIdx.x;
    if (gid < 9 * ECC) {
        int r = gid / ECC;
        atomicAdd(&g_cnt_cc[r * NC + ecc_dst[gid]], 1);
    } else if (gid < 9 * ECC + 3 * ECS) {
        int g = gid - 9 * ECC;
        int t = g / ECS;
        atomicAdd(&g_cnt_cs[t * NS + ecs_dst[g]], 1);
    }
}

__global__ void __launch_bounds__(1024) k_scan() {
    int rel = blockIdx.x;                 // 0..8 cc, 9..11 cs
    int n; int* cnt; int* off; int* cur;
    if (rel < 9) { n = NC; cnt = g_cnt_cc + rel * NC; off = g_off_cc + rel * NC; cur = g_cur_cc + rel * NC; }
    else { int t = rel - 9; n = NS; cnt = g_cnt_cs + t * NS; off = g_off_cs + t * NS; cur = g_cur_cs + t * NS; }
    int tid = threadIdx.x;
    int CH = (n + 1023) / 1024;           // 10 or 1
    int base = tid * CH;
    int loc[10]; int s = 0;
    for (int i = 0; i < CH; i++) {
        int v = (base + i < n) ? cnt[base + i] : 0;
        loc[i] = s; s += v;
    }
    __shared__ int sums[1024];
    sums[tid] = s; __syncthreads();
    for (int o = 1; o < 1024; o <<= 1) {
        int v = (tid >= o) ? sums[tid - o] : 0;
        __syncthreads();
        sums[tid] += v;
        __syncthreads();
    }
    int prefix = (tid == 0) ? 0 : sums[tid - 1];
    for (int i = 0; i < CH; i++) if (base + i < n) {
        int o2 = prefix + loc[i];
        off[base + i] = o2;
        cur[base + i] = o2;
    }
}

__global__ void k_scatter(const int* __restrict__ ecc_src, const int* __restrict__ ecc_dst,
                          const int* __restrict__ ecs_src, const int* __restrict__ ecs_dst) {
    int gid = blockIdx.x * blockDim.x + threadIdx.x;
    if (gid < 9 * ECC) {
        int r = gid / ECC;
        int pos = atomicAdd(&g_cur_cc[r * NC + ecc_dst[gid]], 1);
        g_csr_cc[r * ECC + pos] = ecc_src[gid];
    } else if (gid < 9 * ECC + 3 * ECS) {
        int g = gid - 9 * ECC;
        int t = g / ECS;
        int pos = atomicAdd(&g_cur_cs[t * NS + ecs_dst[g]], 1);
        g_csr_cs[t * ECS + pos] = ecs_src[g];
    }
}

// ---------------- dst-centric aggregation with online softmax ----------------
__global__ void __launch_bounds__(256) k_agg_cc(float* __restrict__ out) {
    int dt = blockIdx.y;                        // dst type
    int warp = threadIdx.x / 32, lane = threadIdx.x % 32;
    int node = blockIdx.x * 8 + warp;
    if (node >= NC) return;

    float outacc[H] = {};
    #pragma unroll 1
    for (int s = 0; s < 3; s++) {
        int r = 3 * s + dt;
        float ad[H], m[H], l[H], acc[H];
        const float* adp = g_ad_cc + ((size_t)r * NC + node) * H;
        #pragma unroll
        for (int h = 0; h < H; h++) { ad[h] = adp[h]; m[h] = NEG_BIG; l[h] = 0.f; acc[h] = 0.f; }
        int beg = g_off_cc[r * NC + node];
        int cnt = g_cnt_cc[r * NC + node];
        const float* Wh  = g_Wh_cc + (size_t)r * NC * HD;
        const float* asb = g_as_cc + (size_t)r * NC * H;
        const int* csr   = g_csr_cc + r * ECC;
        for (int e = 0; e < cnt; e++) {
            int src = __ldg(&csr[beg + e]);
            const float* wrow = Wh + (size_t)src * HD;
            const float* asrc = asb + (size_t)src * H;
            #pragma unroll
            for (int h = 0; h < H; h++) {
                float ev = __ldg(&asrc[h]) + ad[h];
                ev = ev > 0.f ? ev : LALPHA * ev;
                float mn = fmaxf(m[h], ev);
                float c  = __expf(m[h] - mn);
                float p  = __expf(ev - mn);
                l[h]   = l[h] * c + p;
                acc[h] = acc[h] * c + p * __ldg(&wrow[h * Dd + lane]);
                m[h] = mn;
            }
        }
        #pragma unroll
        for (int h = 0; h < H; h++)
            if (l[h] > 0.f) outacc[h] += acc[h] / l[h];
    }
    float* o = out + ((size_t)dt * NC + node) * HD;
    #pragma unroll
    for (int h = 0; h < H; h++) o[h * Dd + lane] = fmaxf(outacc[h], 0.f);
}

__global__ void __launch_bounds__(256) k_agg_state(const float* __restrict__ attn_cs,
                                                   float* __restrict__ out) {
    int warp = threadIdx.x / 32, lane = threadIdx.x % 32;
    int node = blockIdx.x * 8 + warp;
    if (node >= NS) return;

    float self[H], outacc[H];
    #pragma unroll
    for (int h = 0; h < H; h++) {
        self[h] = g_Wh_in[(size_t)node * HD + h * Dd + lane];
        outacc[h] = self[h];
    }
    #pragma unroll 1
    for (int t = 0; t < 3; t++) {
        float ad[H];
        #pragma unroll
        for (int h = 0; h < H; h++) {
            float v = self[h] * attn_cs[(size_t)((t * 2 + 1) * H + h) * Dd + lane];
            #pragma unroll
            for (int o = 16; o > 0; o >>= 1) v += __shfl_xor_sync(0xffffffffu, v, o);
            ad[h] = v;
        }
        float m[H], l[H], acc[H];
        #pragma unroll
        for (int h = 0; h < H; h++) { m[h] = NEG_BIG; l[h] = 0.f; acc[h] = 0.f; }
        int beg = g_off_cs[t * NS + node];
        int cnt = g_cnt_cs[t * NS + node];
        const float* Wh  = g_Wh_cs + (size_t)t * NC * HD;
        const float* asb = g_as_cs + (size_t)t * NC * H;
        const int* csr   = g_csr_cs + t * ECS;
        for (int e = 0; e < cnt; e++) {
            int src = __ldg(&csr[beg + e]);
            const float* wrow = Wh + (size_t)src * HD;
            const float* asrc = asb + (size_t)src * H;
            #pragma unroll
            for (int h = 0; h < H; h++) {
                float ev = __ldg(&asrc[h]) + ad[h];
                ev = ev > 0.f ? ev : LALPHA * ev;
                float mn = fmaxf(m[h], ev);
                float c  = __expf(m[h] - mn);
                float p  = __expf(ev - mn);
                l[h]   = l[h] * c + p;
                acc[h] = acc[h] * c + p * __ldg(&wrow[h * Dd + lane]);
                m[h] = mn;
            }
        }
        #pragma unroll
        for (int h = 0; h < H; h++)
            if (l[h] > 0.f) outacc[h] += acc[h] / l[h];
    }
    float* o = out + (size_t)3 * NC * HD + (size_t)node * HD;
    #pragma unroll
    for (int h = 0; h < H; h++) o[h * Dd + lane] = fmaxf(outacc[h], 0.f);
}

// ---------------- launch ----------------
extern "C" void kernel_launch(void* const* d_in, const int* in_sizes, int n_in,
                              void* d_out, int out_size) {
    const float* f1      = (const float*)d_in[0];
    const float* f2      = (const float*)d_in[1];
    const float* f3      = (const float*)d_in[2];
    const float* fs      = (const float*)d_in[3];
    const float* W_node  = (const float*)d_in[4];
    const float* b_node  = (const float*)d_in[5];
    const float* W_cc    = (const float*)d_in[6];
    const float* b_cc    = (const float*)d_in[7];
    const float* W_cs    = (const float*)d_in[8];
    const float* b_cs    = (const float*)d_in[9];
    const float* W_in    = (const float*)d_in[10];
    const float* b_in    = (const float*)d_in[11];
    const float* attn_cc = (const float*)d_in[12];
    const float* attn_cs = (const float*)d_in[13];
    const int* ecc_src   = (const int*)d_in[14];
    const int* ecc_dst   = (const int*)d_in[15];
    const int* ecs_src   = (const int*)d_in[16];
    const int* ecs_dst   = (const int*)d_in[17];
    float* out = (float*)d_out;

    k_zero_counters<<<(9 * NC + 255) / 256, 256>>>();
    k_wred<<<(21 * INC * H + 255) / 256, 256>>>(W_node, b_node, W_cc, b_cc, W_cs, b_cs, attn_cc, attn_cs);
    k_skinny<<<dim3(1250, 21), 256>>>(f1, f2, f3);
    k_gemm<<<dim3(79, 2, 13), 256>>>(f1, f2, f3, fs, W_cc, b_cc, W_cs, b_cs, W_in, b_in);
    int tot = 9 * ECC + 3 * ECS;
    k_hist<<<(tot + 255) / 256, 256>>>(ecc_dst, ecs_dst);
    k_scan<<<12, 1024>>>();
    k_scatter<<<(tot + 255) / 256, 256>>>(ecc_src, ecc_dst, ecs_src, ecs_dst);
    k_agg_cc<<<dim3(1250, 3), 256>>>(out);
    k_agg_state<<<128, 256>>>(attn_cs, out);
}

// round 3
// speedup vs baseline: 1.1893x; 1.1893x over previous
#include <cuda_runtime.h>
#include <cstdint>

#define H   8
#define Dd  32
#define HD  256
#define NC  10000
#define NS  1024
#define INC 128
#define INS 64
#define ECC 120000
#define ECS 10000
#define LALPHA 0.2f
#define NEG_BIG -1e30f

// ---------------- device scratch (static; no runtime allocation) ----------------
__device__ float g_Wh_cc[9u * NC * HD];     // 92.2 MB
__device__ float g_Wh_cs[3u * NC * HD];     // 30.7 MB
__device__ float g_Wh_in[NS * HD];

__device__ float g_as_cc[9 * NC * H];
__device__ float g_ad_cc[9 * NC * H];
__device__ float g_as_cs[3 * NC * H];
__device__ float g_ad_s[3 * NS * H];

__device__ float g_coef_cc[(size_t)9 * ECC * H];   // unnormalized softmax numerators
__device__ float g_coef_cs[(size_t)3 * ECS * H];
__device__ float g_invs_cc[9 * NC * H];            // 1/sum per (rel,node,h)
__device__ float g_invs_cs[3 * NS * H];

__device__ float g_wred_as[9 * INC * H];
__device__ float g_wred_ad[9 * INC * H];
__device__ float g_wred_as_cs[3 * INC * H];
__device__ float g_wred_ad_s[3 * INS * H];
__device__ float g_bred_as[9 * H];
__device__ float g_bred_ad[9 * H];
__device__ float g_bred_as_cs[3 * H];
__device__ float g_bred_ad_s[3 * H];

__device__ int g_cnt_cc[9 * NC];
__device__ int g_off_cc[9 * NC];
__device__ int g_cur_cc[9 * NC];
__device__ int g_csr_cc[9 * ECC];
__device__ int g_cnt_cs[3 * NS];
__device__ int g_off_cs[3 * NS];
__device__ int g_cur_cs[3 * NS];
__device__ int g_csr_cs[3 * ECS];

// ---------------- zero counters ----------------
__global__ void k_zero_counters() {
    int i = blockIdx.x * blockDim.x + threadIdx.x;
    if (i < 9 * NC) g_cnt_cc[i] = 0;
    if (i < 3 * NS) g_cnt_cs[i] = 0;
}

// ---------------- reduce attention vectors into weights ----------------
// a = (feat @ W + b) . attn  ==  feat @ (W . attn) + (b . attn)
__global__ void k_wred(const float* __restrict__ W_node, const float* __restrict__ b_node,
                       const float* __restrict__ W_cc,   const float* __restrict__ b_cc,
                       const float* __restrict__ W_cs,   const float* __restrict__ b_cs,
                       const float* __restrict__ W_in,   const float* __restrict__ b_in,
                       const float* __restrict__ attn_cc, const float* __restrict__ attn_cs) {
    int gid = blockIdx.x * blockDim.x + threadIdx.x;
    if (gid >= 24 * INC * H) return;
    int j   = gid / (INC * H);
    int rem = gid % (INC * H);
    int k = rem / H, h = rem % H;
    const float *Wsrc, *att, *bvec;
    float *dst, *bdst;
    int Kin = INC;
    if (j < 9) {                       // a_src cc rel j
        Wsrc = W_cc + (size_t)j * INC * HD;
        att  = attn_cc + (size_t)(j * 2 + 0) * HD;
        bvec = b_cc + (size_t)j * HD;
        dst  = g_wred_as + j * INC * H; bdst = g_bred_as + j * H;
    } else if (j < 18) {               // a_dst cc rel r (W_node[r%3], attn_cc[r][1])
        int r = j - 9;
        Wsrc = W_node + (size_t)(r % 3) * INC * HD;
        att  = attn_cc + (size_t)(r * 2 + 1) * HD;
        bvec = b_node + (size_t)(r % 3) * HD;
        dst  = g_wred_ad + r * INC * H; bdst = g_bred_ad + r * H;
    } else if (j < 21) {               // a_src cs rel t
        int t = j - 18;
        Wsrc = W_cs + (size_t)t * INC * HD;
        att  = attn_cs + (size_t)(t * 2 + 0) * HD;
        bvec = b_cs + (size_t)t * HD;
        dst  = g_wred_as_cs + t * INC * H; bdst = g_bred_as_cs + t * H;
    } else {                           // a_dst state rel t (W_in, attn_cs[t][1])
        int t = j - 21;
        Wsrc = W_in;
        att  = attn_cs + (size_t)(t * 2 + 1) * HD;
        bvec = b_in;
        dst  = g_wred_ad_s + t * INS * H; bdst = g_bred_ad_s + t * H;
        Kin = INS;
    }
    if (k >= Kin) return;
    float s = 0.f;
    #pragma unroll
    for (int d = 0; d < Dd; d++)
        s += Wsrc[(size_t)k * HD + h * Dd + d] * att[h * Dd + d];
    dst[k * H + h] = s;
    if (k == 0) {
        float bs = 0.f;
        #pragma unroll
        for (int d = 0; d < Dd; d++) bs += bvec[h * Dd + d] * att[h * Dd + d];
        bdst[h] = bs;
    }
}

// ---------------- skinny GEMMs: per-node attention scalars --------
__global__ void __launch_bounds__(256) k_skinny(const float* __restrict__ f1,
                                                const float* __restrict__ f2,
                                                const float* __restrict__ f3,
                                                const float* __restrict__ fs) {
    int y = blockIdx.y;
    const float* feat; const float* wred; const float* bred; float* outp;
    int Kin = INC, nNodes = NC;
    {
        if (y < 9)       { int sel = y / 3; feat = (sel==0)?f1:(sel==1)?f2:f3;
                           wred = g_wred_as + y * INC * H;    bred = g_bred_as + y * H;    outp = g_as_cc + (size_t)y * NC * H; }
        else if (y < 18) { int r = y - 9; int sel = r % 3; feat = (sel==0)?f1:(sel==1)?f2:f3;
                           wred = g_wred_ad + r * INC * H;    bred = g_bred_ad + r * H;    outp = g_ad_cc + (size_t)r * NC * H; }
        else if (y < 21) { int t = y - 18; feat = (t==0)?f1:(t==1)?f2:f3;
                           wred = g_wred_as_cs + t * INC * H; bred = g_bred_as_cs + t * H; outp = g_as_cs + (size_t)t * NC * H; }
        else             { int t = y - 21; feat = fs; Kin = INS; nNodes = NS;
                           wred = g_wred_ad_s + t * INS * H;  bred = g_bred_ad_s + t * H;  outp = g_ad_s + (size_t)t * NS * H; }
    }
    __shared__ float Wst[H * INC];   // transposed: [h][k]
    __shared__ float bs[H];
    for (int idx = threadIdx.x; idx < Kin * H; idx += 256) {
        int h = idx / Kin, k = idx % Kin;
        Wst[h * INC + k] = wred[k * H + h];
    }
    if (threadIdx.x < H) bs[threadIdx.x] = bred[threadIdx.x];
    __syncthreads();

    int warp = threadIdx.x / 32, lane = threadIdx.x % 32;
    int node = blockIdx.x * 8 + warp;
    if (node >= nNodes) return;
    const float* frow = feat + (size_t)node * Kin;
    float p[H] = {};
    for (int c = 0; c < Kin / 32; c++) {
        int k = c * 32 + lane;
        float f = frow[k];
        #pragma unroll
        for (int h = 0; h < H; h++) p[h] += f * Wst[h * INC + k];
    }
    float mine = 0.f;
    #pragma unroll
    for (int h = 0; h < H; h++) {
        float v = p[h];
        #pragma unroll
        for (int o = 16; o > 0; o >>= 1) v += __shfl_xor_sync(0xffffffffu, v, o);
        if (lane == h) mine = v;
    }
    if (lane < H) outp[(size_t)node * H + lane] = mine + bs[lane];
}

// ---------------- big GEMMs: 13 jobs, double-buffered -------------------
__global__ void __launch_bounds__(256, 2) k_gemm(const float* __restrict__ f1, const float* __restrict__ f2,
                                                 const float* __restrict__ f3, const float* __restrict__ fs,
                                                 const float* __restrict__ Wcc, const float* __restrict__ bcc,
                                                 const float* __restrict__ Wcs, const float* __restrict__ bcs,
                                                 const float* __restrict__ Win, const float* __restrict__ bin) {
    int z = blockIdx.z;
    const float* A; const float* W; const float* bptr; float* outp; int M, K;
    if (z < 9) {
        int s = z / 3;
        A = (s == 0) ? f1 : (s == 1) ? f2 : f3;
        W = Wcc + (size_t)z * INC * HD; bptr = bcc + (size_t)z * HD;
        outp = g_Wh_cc + (size_t)z * NC * HD; M = NC; K = INC;
    } else if (z < 12) {
        int t = z - 9;
        A = (t == 0) ? f1 : (t == 1) ? f2 : f3;
        W = Wcs + (size_t)t * INC * HD; bptr = bcs + (size_t)t * HD;
        outp = g_Wh_cs + (size_t)t * NC * HD; M = NC; K = INC;
    } else {
        A = fs; W = Win; bptr = bin; outp = g_Wh_in; M = NS; K = INS;
    }
    int row0 = blockIdx.x * 128;
    if (row0 >= M) return;
    int col0 = blockIdx.y * 128;

    __shared__ float As[2][16][128];
    __shared__ float Bs[2][16][128];
    int tid = threadIdx.x;
    int tx = tid % 16, ty = tid / 16;
    float acc[8][8] = {};
    float4 la[2], lb[2];

    // per-thread load geometry
    int ia_r[2], ia_c[2], ib_r[2], ib_c[2];
    #pragma unroll
    for (int i = 0; i < 2; i++) {
        int idx = tid * 2 + i;
        ia_r[i] = idx >> 2;  ia_c[i] = (idx & 3) * 4;
        ib_r[i] = idx >> 5;  ib_c[i] = (idx & 31) * 4;
    }

    // prologue: tile 0
    #pragma unroll
    for (int i = 0; i < 2; i++) {
        la[i] = make_float4(0.f, 0.f, 0.f, 0.f);
        if (row0 + ia_r[i] < M)
            la[i] = *(const float4*)(A + (size_t)(row0 + ia_r[i]) * K + ia_c[i]);
        lb[i] = *(const float4*)(W + (size_t)ib_r[i] * HD + col0 + ib_c[i]);
    }
    #pragma unroll
    for (int i = 0; i < 2; i++) {
        As[0][ia_c[i] + 0][ia_r[i]] = la[i].x; As[0][ia_c[i] + 1][ia_r[i]] = la[i].y;
        As[0][ia_c[i] + 2][ia_r[i]] = la[i].z; As[0][ia_c[i] + 3][ia_r[i]] = la[i].w;
        *(float4*)&Bs[0][ib_r[i]][ib_c[i]] = lb[i];
    }
    __syncthreads();

    int cur = 0;
    for (int kt = 0; kt < K; kt += 16) {
        bool nxt = (kt + 16) < K;
        if (nxt) {
            #pragma unroll
            for (int i = 0; i < 2; i++) {
                la[i] = make_float4(0.f, 0.f, 0.f, 0.f);
                if (row0 + ia_r[i] < M)
                    la[i] = *(const float4*)(A + (size_t)(row0 + ia_r[i]) * K + kt + 16 + ia_c[i]);
                lb[i] = *(const float4*)(W + (size_t)(kt + 16 + ib_r[i]) * HD + col0 + ib_c[i]);
            }
        }
        #pragma unroll
        for (int k = 0; k < 16; k++) {
            float a[8], b[8];
            *(float4*)&a[0] = *(const float4*)&As[cur][k][ty * 8];
            *(float4*)&a[4] = *(const float4*)&As[cur][k][ty * 8 + 4];
            *(float4*)&b[0] = *(const float4*)&Bs[cur][k][tx * 8];
            *(float4*)&b[4] = *(const float4*)&Bs[cur][k][tx * 8 + 4];
            #pragma unroll
            for (int i = 0; i < 8; i++)
                #pragma unroll
                for (int j = 0; j < 8; j++)
                    acc[i][j] += a[i] * b[j];
        }
        if (nxt) {
            int nb = cur ^ 1;
            #pragma unroll
            for (int i = 0; i < 2; i++) {
                As[nb][ia_c[i] + 0][ia_r[i]] = la[i].x; As[nb][ia_c[i] + 1][ia_r[i]] = la[i].y;
                As[nb][ia_c[i] + 2][ia_r[i]] = la[i].z; As[nb][ia_c[i] + 3][ia_r[i]] = la[i].w;
                *(float4*)&Bs[nb][ib_r[i]][ib_c[i]] = lb[i];
            }
        }
        __syncthreads();
        cur ^= 1;
    }

    float bb[8];
    #pragma unroll
    for (int j = 0; j < 8; j++) bb[j] = bptr[col0 + tx * 8 + j];
    #pragma unroll
    for (int i = 0; i < 8; i++) {
        int r = row0 + ty * 8 + i;
        if (r < M) {
            float* orow = outp + (size_t)r * HD + col0 + tx * 8;
            float4 v0, v1;
            v0.x = acc[i][0] + bb[0]; v0.y = acc[i][1] + bb[1];
            v0.z = acc[i][2] + bb[2]; v0.w = acc[i][3] + bb[3];
            v1.x = acc[i][4] + bb[4]; v1.y = acc[i][5] + bb[5];
            v1.z = acc[i][6] + bb[6]; v1.w = acc[i][7] + bb[7];
            *(float4*)(orow)     = v0;
            *(float4*)(orow + 4) = v1;
        }
    }
}

// ---------------- CSR build: histogram, scan, scatter ----------------
__global__ void k_hist(const int* __restrict__ ecc_dst, const int* __restrict__ ecs_dst) {
    int gid = blockIdx.x * blockDim.x + threadIdx.x;
    if (gid < 9 * ECC) {
        int r = gid / ECC;
        atomicAdd(&g_cnt_cc[r * NC + ecc_dst[gid]], 1);
    } else if (gid < 9 * ECC + 3 * ECS) {
        int g = gid - 9 * ECC;
        int t = g / ECS;
        atomicAdd(&g_cnt_cs[t * NS + ecs_dst[g]], 1);
    }
}

__global__ void __launch_bounds__(1024) k_scan() {
    int rel = blockIdx.x;                 // 0..8 cc, 9..11 cs
    int n; int* cnt; int* off; int* cur;
    if (rel < 9) { n = NC; cnt = g_cnt_cc + rel * NC; off = g_off_cc + rel * NC; cur = g_cur_cc + rel * NC; }
    else { int t = rel - 9; n = NS; cnt = g_cnt_cs + t * NS; off = g_off_cs + t * NS; cur = g_cur_cs + t * NS; }
    int tid = threadIdx.x;
    int CH = (n + 1023) / 1024;           // 10 or 1
    int base = tid * CH;
    int loc[10]; int s = 0;
    for (int i = 0; i < CH; i++) {
        int v = (base + i < n) ? cnt[base + i] : 0;
        loc[i] = s; s += v;
    }
    __shared__ int sums[1024];
    sums[tid] = s; __syncthreads();
    for (int o = 1; o < 1024; o <<= 1) {
        int v = (tid >= o) ? sums[tid - o] : 0;
        __syncthreads();
        sums[tid] += v;
        __syncthreads();
    }
    int prefix = (tid == 0) ? 0 : sums[tid - 1];
    for (int i = 0; i < CH; i++) if (base + i < n) {
        int o2 = prefix + loc[i];
        off[base + i] = o2;
        cur[base + i] = o2;
    }
}

__global__ void k_scatter(const int* __restrict__ ecc_src, const int* __restrict__ ecc_dst,
                          const int* __restrict__ ecs_src, const int* __restrict__ ecs_dst) {
    int gid = blockIdx.x * blockDim.x + threadIdx.x;
    if (gid < 9 * ECC) {
        int r = gid / ECC;
        int pos = atomicAdd(&g_cur_cc[r * NC + ecc_dst[gid]], 1);
        g_csr_cc[r * ECC + pos] = ecc_src[gid];
    } else if (gid < 9 * ECC + 3 * ECS) {
        int g = gid - 9 * ECC;
        int t = g / ECS;
        int pos = atomicAdd(&g_cur_cs[t * NS + ecs_dst[g]], 1);
        g_csr_cs[t * ECS + pos] = ecs_src[g];
    }
}

// ---------------- edge softmax coefficients: lanes parallel over edges ----------------
__device__ __forceinline__ float lrelu(float x) { return x > 0.f ? x : LALPHA * x; }

__global__ void __launch_bounds__(256) k_coef() {
    int y = blockIdx.y;                 // 0..8 cc, 9..11 cs
    int warp = threadIdx.x >> 5, lane = threadIdx.x & 31;
    int node = blockIdx.x * 8 + warp;
    int n; const int* csr; const int* offp; const int* cntp;
    const float* asb; const float* adp; float* coef; float* invsp;
    if (y < 9) {
        n = NC; csr = g_csr_cc + (size_t)y * ECC;
        offp = g_off_cc + y * NC; cntp = g_cnt_cc + y * NC;
        asb = g_as_cc + (size_t)y * NC * H;
        adp = g_ad_cc + (size_t)y * NC * H;
        coef = g_coef_cc + (size_t)y * ECC * H;
        invsp = g_invs_cc + (size_t)y * NC * H;
    } else {
        int t = y - 9;
        n = NS; csr = g_csr_cs + (size_t)t * ECS;
        offp = g_off_cs + t * NS; cntp = g_cnt_cs + t * NS;
        asb = g_as_cs + (size_t)t * NC * H;
        adp = g_ad_s + (size_t)t * NS * H;
        coef = g_coef_cs + (size_t)t * ECS * H;
        invsp = g_invs_cs + (size_t)t * NS * H;
    }
    if (node >= n) return;
    int beg = offp[node], cnt = cntp[node];

    float ad[H];
    {
        float4 a0 = *(const float4*)(adp + (size_t)node * H);
        float4 a1 = *(const float4*)(adp + (size_t)node * H + 4);
        ad[0]=a0.x; ad[1]=a0.y; ad[2]=a0.z; ad[3]=a0.w;
        ad[4]=a1.x; ad[5]=a1.y; ad[6]=a1.z; ad[7]=a1.w;
    }

    float m[H];
    #pragma unroll
    for (int h = 0; h < H; h++) m[h] = NEG_BIG;
    float evr[2][H];
    int myCnt = 0;
    for (int e = lane; e < cnt; e += 32) {
        int src = __ldg(&csr[beg + e]);
        float4 s0 = *(const float4*)(asb + (size_t)src * H);
        float4 s1 = *(const float4*)(asb + (size_t)src * H + 4);
        float ev[H];
        ev[0]=lrelu(s0.x+ad[0]); ev[1]=lrelu(s0.y+ad[1]); ev[2]=lrelu(s0.z+ad[2]); ev[3]=lrelu(s0.w+ad[3]);
        ev[4]=lrelu(s1.x+ad[4]); ev[5]=lrelu(s1.y+ad[5]); ev[6]=lrelu(s1.z+ad[6]); ev[7]=lrelu(s1.w+ad[7]);
        if (myCnt < 2) {
            #pragma unroll
            for (int h = 0; h < H; h++) evr[myCnt][h] = ev[h];
        }
        #pragma unroll
        for (int h = 0; h < H; h++) m[h] = fmaxf(m[h], ev[h]);
        myCnt++;
    }
    #pragma unroll
    for (int h = 0; h < H; h++) {
        #pragma unroll
        for (int o = 16; o > 0; o >>= 1) m[h] = fmaxf(m[h], __shfl_xor_sync(0xffffffffu, m[h], o));
    }
    float sum[H];
    #pragma unroll
    for (int h = 0; h < H; h++) sum[h] = 0.f;
    int idx = 0;
    for (int e = lane; e < cnt; e += 32) {
        float ev[H];
        if (idx < 2) {
            #pragma unroll
            for (int h = 0; h < H; h++) ev[h] = evr[idx][h];
        } else {
            int src = __ldg(&csr[beg + e]);
            float4 s0 = *(const float4*)(asb + (size_t)src * H);
            float4 s1 = *(const float4*)(asb + (size_t)src * H + 4);
            ev[0]=lrelu(s0.x+ad[0]); ev[1]=lrelu(s0.y+ad[1]); ev[2]=lrelu(s0.z+ad[2]); ev[3]=lrelu(s0.w+ad[3]);
            ev[4]=lrelu(s1.x+ad[4]); ev[5]=lrelu(s1.y+ad[5]); ev[6]=lrelu(s1.z+ad[6]); ev[7]=lrelu(s1.w+ad[7]);
        }
        float p[H];
        #pragma unroll
        for (int h = 0; h < H; h++) { p[h] = __expf(ev[h] - m[h]); sum[h] += p[h]; }
        float* cp = coef + (size_t)(beg + e) * H;
        float4 c0, c1;
        c0.x=p[0]; c0.y=p[1]; c0.z=p[2]; c0.w=p[3];
        c1.x=p[4]; c1.y=p[5]; c1.z=p[6]; c1.w=p[7];
        *(float4*)cp = c0; *(float4*)(cp + 4) = c1;
        idx++;
    }
    #pragma unroll
    for (int h = 0; h < H; h++) {
        #pragma unroll
        for (int o = 16; o > 0; o >>= 1) sum[h] += __shfl_xor_sync(0xffffffffu, sum[h], o);
    }
    if (lane == 0) {
        float iv[H];
        #pragma unroll
        for (int h = 0; h < H; h++) iv[h] = (cnt > 0) ? 1.f / sum[h] : 0.f;
        float* op = invsp + (size_t)node * H;
        float4 v0, v1;
        v0.x=iv[0]; v0.y=iv[1]; v0.z=iv[2]; v0.w=iv[3];
        v1.x=iv[4]; v1.y=iv[5]; v1.z=iv[6]; v1.w=iv[7];
        *(float4*)op = v0; *(float4*)(op + 4) = v1;
    }
}

// ---------------- weighted gather: lane owns 8 contiguous channels ----------------
__global__ void __launch_bounds__(256) k_gather_cc(float* __restrict__ out) {
    int dt = blockIdx.y;
    int warp = threadIdx.x >> 5, lane = threadIdx.x & 31;
    int node = blockIdx.x * 8 + warp;
    if (node >= NC) return;
    int hq = lane >> 2;            // head this lane's 8 channels belong to

    float outacc[8] = {};
    #pragma unroll 1
    for (int s = 0; s < 3; s++) {
        int r = 3 * s + dt;
        int beg = g_off_cc[r * NC + node];
        int cnt = g_cnt_cc[r * NC + node];
        if (cnt == 0) continue;
        float invs = g_invs_cc[((size_t)r * NC + node) * H + hq];
        const float* Wh = g_Wh_cc + (size_t)r * NC * HD;
        const int* csr = g_csr_cc + (size_t)r * ECC;
        const float* coef = g_coef_cc + (size_t)r * ECC * H;
        float acc[8] = {};
        #pragma unroll 4
        for (int e = 0; e < cnt; e++) {
            int src = __ldg(&csr[beg + e]);
            float cf = __ldg(&coef[(size_t)(beg + e) * H + hq]);
            const float* wr = Wh + (size_t)src * HD + lane * 8;
            float4 w0 = *(const float4*)wr;
            float4 w1 = *(const float4*)(wr + 4);
            acc[0] += cf * w0.x; acc[1] += cf * w0.y; acc[2] += cf * w0.z; acc[3] += cf * w0.w;
            acc[4] += cf * w1.x; acc[5] += cf * w1.y; acc[6] += cf * w1.z; acc[7] += cf * w1.w;
        }
        #pragma unroll
        for (int j = 0; j < 8; j++) outacc[j] += acc[j] * invs;
    }
    float* o = out + ((size_t)dt * NC + node) * HD + lane * 8;
    float4 v0, v1;
    v0.x = fmaxf(outacc[0], 0.f); v0.y = fmaxf(outacc[1], 0.f);
    v0.z = fmaxf(outacc[2], 0.f); v0.w = fmaxf(outacc[3], 0.f);
    v1.x = fmaxf(outacc[4], 0.f); v1.y = fmaxf(outacc[5], 0.f);
    v1.z = fmaxf(outacc[6], 0.f); v1.w = fmaxf(outacc[7], 0.f);
    *(float4*)o = v0; *(float4*)(o + 4) = v1;
}

__global__ void __launch_bounds__(256) k_gather_state(float* __restrict__ out) {
    int warp = threadIdx.x >> 5, lane = threadIdx.x & 31;
    int node = blockIdx.x * 8 + warp;
    if (node >= NS) return;
    int hq = lane >> 2;

    float outacc[8];
    {
        const float* sp = g_Wh_in + (size_t)node * HD + lane * 8;
        float4 s0 = *(const float4*)sp;
        float4 s1 = *(const float4*)(sp + 4);
        outacc[0]=s0.x; outacc[1]=s0.y; outacc[2]=s0.z; outacc[3]=s0.w;
        outacc[4]=s1.x; outacc[5]=s1.y; outacc[6]=s1.z; outacc[7]=s1.w;
    }
    #pragma unroll 1
    for (int t = 0; t < 3; t++) {
        int beg = g_off_cs[t * NS + node];
        int cnt = g_cnt_cs[t * NS + node];
        if (cnt == 0) continue;
        float invs = g_invs_cs[((size_t)t * NS + node) * H + hq];
        const float* Wh = g_Wh_cs + (size_t)t * NC * HD;
        const int* csr = g_csr_cs + (size_t)t * ECS;
        const float* coef = g_coef_cs + (size_t)t * ECS * H;
        float acc[8] = {};
        #pragma unroll 4
        for (int e = 0; e < cnt; e++) {
            int src = __ldg(&csr[beg + e]);
            float cf = __ldg(&coef[(size_t)(beg + e) * H + hq]);
            const float* wr = Wh + (size_t)src * HD + lane * 8;
            float4 w0 = *(const float4*)wr;
            float4 w1 = *(const float4*)(wr + 4);
            acc[0] += cf * w0.x; acc[1] += cf * w0.y; acc[2] += cf * w0.z; acc[3] += cf * w0.w;
            acc[4] += cf * w1.x; acc[5] += cf * w1.y; acc[6] += cf * w1.z; acc[7] += cf * w1.w;
        }
        #pragma unroll
        for (int j = 0; j < 8; j++) outacc[j] += acc[j] * invs;
    }
    float* o = out + (size_t)3 * NC * HD + (size_t)node * HD + lane * 8;
    float4 v0, v1;
    v0.x = fmaxf(outacc[0], 0.f); v0.y = fmaxf(outacc[1], 0.f);
    v0.z = fmaxf(outacc[2], 0.f); v0.w = fmaxf(outacc[3], 0.f);
    v1.x = fmaxf(outacc[4], 0.f); v1.y = fmaxf(outacc[5], 0.f);
    v1.z = fmaxf(outacc[6], 0.f); v1.w = fmaxf(outacc[7], 0.f);
    *(float4*)o = v0; *(float4*)(o + 4) = v1;
}

// ---------------- launch ----------------
extern "C" void kernel_launch(void* const* d_in, const int* in_sizes, int n_in,
                              void* d_out, int out_size) {
    const float* f1      = (const float*)d_in[0];
    const float* f2      = (const float*)d_in[1];
    const float* f3      = (const float*)d_in[2];
    const float* fs      = (const float*)d_in[3];
    const float* W_node  = (const float*)d_in[4];
    const float* b_node  = (const float*)d_in[5];
    const float* W_cc    = (const float*)d_in[6];
    const float* b_cc    = (const float*)d_in[7];
    const float* W_cs    = (const float*)d_in[8];
    const float* b_cs    = (const float*)d_in[9];
    const float* W_in    = (const float*)d_in[10];
    const float* b_in    = (const float*)d_in[11];
    const float* attn_cc = (const float*)d_in[12];
    const float* attn_cs = (const float*)d_in[13];
    const int* ecc_src   = (const int*)d_in[14];
    const int* ecc_dst   = (const int*)d_in[15];
    const int* ecs_src   = (const int*)d_in[16];
    const int* ecs_dst   = (const int*)d_in[17];
    float* out = (float*)d_out;

    k_zero_counters<<<(9 * NC + 255) / 256, 256>>>();
    k_wred<<<(24 * INC * H + 255) / 256, 256>>>(W_node, b_node, W_cc, b_cc, W_cs, b_cs, W_in, b_in, attn_cc, attn_cs);
    k_skinny<<<dim3(1250, 24), 256>>>(f1, f2, f3, fs);
    int tot = 9 * ECC + 3 * ECS;
    k_hist<<<(tot + 255) / 256, 256>>>(ecc_dst, ecs_dst);
    k_scan<<<12, 1024>>>();
    k_scatter<<<(tot + 255) / 256, 256>>>(ecc_src, ecc_dst, ecs_src, ecs_dst);
    k_coef<<<dim3(1250, 12), 256>>>();
    k_gemm<<<dim3(79, 2, 13), 256>>>(f1, f2, f3, fs, W_cc, b_cc, W_cs, b_cs, W_in, b_in);
    k_gather_cc<<<dim3(1250, 3), 256>>>(out);
    k_gather_state<<<128, 256>>>(out);   // FIX: 128 blocks x 8 warps = 1024 = NS
}

// round 4
// speedup vs baseline: 1.5413x; 1.2960x over previous
#include <cuda_runtime.h>
#include <cstdint>

#define H   8
#define Dd  32
#define HD  256
#define NC  10000
#define NS  1024
#define INC 128
#define INS 64
#define ECC 120000
#define ECS 10000
#define LALPHA 0.2f
#define NEG_BIG -1e30f

// ---------------- device scratch (static; no runtime allocation) ----------------
__device__ float g_Wh_cc[9u * NC * HD];     // 92.2 MB
__device__ float g_Wh_cs[3u * NC * HD];     // 30.7 MB
__device__ float g_Wh_in[NS * HD];

__device__ float g_as_cc[9 * NC * H];
__device__ float g_ad_cc[9 * NC * H];
__device__ float g_as_cs[3 * NC * H];
__device__ float g_ad_s[3 * NS * H];

__device__ float g_coef_cc[(size_t)9 * ECC * H];   // unnormalized softmax numerators
__device__ float g_coef_cs[(size_t)3 * ECS * H];
__device__ float g_invs_cc[9 * NC * H];            // 1/sum per (rel,node,h)
__device__ float g_invs_cs[3 * NS * H];

__device__ float g_wred_as[9 * INC * H];
__device__ float g_wred_ad[9 * INC * H];
__device__ float g_wred_as_cs[3 * INC * H];
__device__ float g_wred_ad_s[3 * INS * H];
__device__ float g_bred_as[9 * H];
__device__ float g_bred_ad[9 * H];
__device__ float g_bred_as_cs[3 * H];
__device__ float g_bred_ad_s[3 * H];

__device__ int g_cnt_cc[9 * NC];
__device__ int g_off_cc[9 * NC];
__device__ int g_cur_cc[9 * NC];
__device__ int g_csr_cc[9 * ECC];
__device__ int g_cnt_cs[3 * NS];
__device__ int g_off_cs[3 * NS];
__device__ int g_cur_cs[3 * NS];
__device__ int g_csr_cs[3 * ECS];

// ---------------- zero counters ----------------
__global__ void k_zero_counters() {
    int i = blockIdx.x * blockDim.x + threadIdx.x;
    if (i < 9 * NC) g_cnt_cc[i] = 0;
    if (i < 3 * NS) g_cnt_cs[i] = 0;
}

// ---------------- reduce attention vectors into weights ----------------
__global__ void k_wred(const float* __restrict__ W_node, const float* __restrict__ b_node,
                       const float* __restrict__ W_cc,   const float* __restrict__ b_cc,
                       const float* __restrict__ W_cs,   const float* __restrict__ b_cs,
                       const float* __restrict__ W_in,   const float* __restrict__ b_in,
                       const float* __restrict__ attn_cc, const float* __restrict__ attn_cs) {
    int gid = blockIdx.x * blockDim.x + threadIdx.x;
    if (gid >= 24 * INC * H) return;
    int j   = gid / (INC * H);
    int rem = gid % (INC * H);
    int k = rem / H, h = rem % H;
    const float *Wsrc, *att, *bvec;
    float *dst, *bdst;
    int Kin = INC;
    if (j < 9) {
        Wsrc = W_cc + (size_t)j * INC * HD;
        att  = attn_cc + (size_t)(j * 2 + 0) * HD;
        bvec = b_cc + (size_t)j * HD;
        dst  = g_wred_as + j * INC * H; bdst = g_bred_as + j * H;
    } else if (j < 18) {
        int r = j - 9;
        Wsrc = W_node + (size_t)(r % 3) * INC * HD;
        att  = attn_cc + (size_t)(r * 2 + 1) * HD;
        bvec = b_node + (size_t)(r % 3) * HD;
        dst  = g_wred_ad + r * INC * H; bdst = g_bred_ad + r * H;
    } else if (j < 21) {
        int t = j - 18;
        Wsrc = W_cs + (size_t)t * INC * HD;
        att  = attn_cs + (size_t)(t * 2 + 0) * HD;
        bvec = b_cs + (size_t)t * HD;
        dst  = g_wred_as_cs + t * INC * H; bdst = g_bred_as_cs + t * H;
    } else {
        int t = j - 21;
        Wsrc = W_in;
        att  = attn_cs + (size_t)(t * 2 + 1) * HD;
        bvec = b_in;
        dst  = g_wred_ad_s + t * INS * H; bdst = g_bred_ad_s + t * H;
        Kin = INS;
    }
    if (k >= Kin) return;
    float s = 0.f;
    #pragma unroll
    for (int d = 0; d < Dd; d++)
        s += Wsrc[(size_t)k * HD + h * Dd + d] * att[h * Dd + d];
    dst[k * H + h] = s;
    if (k == 0) {
        float bs = 0.f;
        #pragma unroll
        for (int d = 0; d < Dd; d++) bs += bvec[h * Dd + d] * att[h * Dd + d];
        bdst[h] = bs;
    }
}

// ---------------- skinny GEMMs (fp32 — keeps softmax logits exact) --------
__global__ void __launch_bounds__(256) k_skinny(const float* __restrict__ f1,
                                                const float* __restrict__ f2,
                                                const float* __restrict__ f3,
                                                const float* __restrict__ fs) {
    int y = blockIdx.y;
    const float* feat; const float* wred; const float* bred; float* outp;
    int Kin = INC, nNodes = NC;
    {
        if (y < 9)       { int sel = y / 3; feat = (sel==0)?f1:(sel==1)?f2:f3;
                           wred = g_wred_as + y * INC * H;    bred = g_bred_as + y * H;    outp = g_as_cc + (size_t)y * NC * H; }
        else if (y < 18) { int r = y - 9; int sel = r % 3; feat = (sel==0)?f1:(sel==1)?f2:f3;
                           wred = g_wred_ad + r * INC * H;    bred = g_bred_ad + r * H;    outp = g_ad_cc + (size_t)r * NC * H; }
        else if (y < 21) { int t = y - 18; feat = (t==0)?f1:(t==1)?f2:f3;
                           wred = g_wred_as_cs + t * INC * H; bred = g_bred_as_cs + t * H; outp = g_as_cs + (size_t)t * NC * H; }
        else             { int t = y - 21; feat = fs; Kin = INS; nNodes = NS;
                           wred = g_wred_ad_s + t * INS * H;  bred = g_bred_ad_s + t * H;  outp = g_ad_s + (size_t)t * NS * H; }
    }
    __shared__ float Wst[H * INC];
    __shared__ float bs[H];
    for (int idx = threadIdx.x; idx < Kin * H; idx += 256) {
        int h = idx / Kin, k = idx % Kin;
        Wst[h * INC + k] = wred[k * H + h];
    }
    if (threadIdx.x < H) bs[threadIdx.x] = bred[threadIdx.x];
    __syncthreads();

    int warp = threadIdx.x / 32, lane = threadIdx.x % 32;
    int node = blockIdx.x * 8 + warp;
    if (node >= nNodes) return;
    const float* frow = feat + (size_t)node * Kin;
    float p[H] = {};
    for (int c = 0; c < Kin / 32; c++) {
        int k = c * 32 + lane;
        float f = frow[k];
        #pragma unroll
        for (int h = 0; h < H; h++) p[h] += f * Wst[h * INC + k];
    }
    float mine = 0.f;
    #pragma unroll
    for (int h = 0; h < H; h++) {
        float v = p[h];
        #pragma unroll
        for (int o = 16; o > 0; o >>= 1) v += __shfl_xor_sync(0xffffffffu, v, o);
        if (lane == h) mine = v;
    }
    if (lane < H) outp[(size_t)node * H + lane] = mine + bs[lane];
}

// ---------------- TF32 tensor-core GEMM helpers ----------------
__device__ __forceinline__ unsigned f2tf32(float x) {
    unsigned u; asm("cvt.rna.tf32.f32 %0, %1;" : "=r"(u) : "f"(x)); return u;
}
__device__ __forceinline__ void mma_tf32(float c[4], const unsigned a[4], const unsigned b[2]) {
    asm volatile("mma.sync.aligned.m16n8k8.row.col.f32.tf32.tf32.f32 "
        "{%0,%1,%2,%3}, {%4,%5,%6,%7}, {%8,%9}, {%0,%1,%2,%3};"
        : "+f"(c[0]), "+f"(c[1]), "+f"(c[2]), "+f"(c[3])
        : "r"(a[0]), "r"(a[1]), "r"(a[2]), "r"(a[3]), "r"(b[0]), "r"(b[1]));
}

// ---------------- big GEMMs: 13 jobs, TF32 MMA, 128x128 tiles ----------------
// Messages only (softmax logits stay fp32 via k_skinny) -> TF32 error ~3e-4 on output.
__global__ void __launch_bounds__(256, 2) k_gemm(const float* __restrict__ f1, const float* __restrict__ f2,
                                                 const float* __restrict__ f3, const float* __restrict__ fs,
                                                 const float* __restrict__ Wcc, const float* __restrict__ bcc,
                                                 const float* __restrict__ Wcs, const float* __restrict__ bcs,
                                                 const float* __restrict__ Win, const float* __restrict__ bin) {
    int z = blockIdx.z;
    const float* A; const float* W; const float* bptr; float* outp; int M, K;
    if (z < 9) {
        int s = z / 3;
        A = (s == 0) ? f1 : (s == 1) ? f2 : f3;
        W = Wcc + (size_t)z * INC * HD; bptr = bcc + (size_t)z * HD;
        outp = g_Wh_cc + (size_t)z * NC * HD; M = NC; K = INC;
    } else if (z < 12) {
        int t = z - 9;
        A = (t == 0) ? f1 : (t == 1) ? f2 : f3;
        W = Wcs + (size_t)t * INC * HD; bptr = bcs + (size_t)t * HD;
        outp = g_Wh_cs + (size_t)t * NC * HD; M = NC; K = INC;
    } else {
        A = fs; W = Win; bptr = bin; outp = g_Wh_in; M = NS; K = INS;
    }
    int row0 = blockIdx.x * 128;
    if (row0 >= M) return;
    int col0 = blockIdx.y * 128;

    // K-tile = 16, double-buffered. Pads chosen for conflict-free fragment loads.
    __shared__ unsigned As[2][128][20];   // [m][k], pad 20
    __shared__ unsigned Bs[2][16][132];   // [k][n], pad 132

    int tid = threadIdx.x;
    int warp = tid >> 5, lane = tid & 31;
    int wm = warp & 3, wn = warp >> 2;      // 4x2 warp grid -> warp tile 32x64
    int gr = lane >> 2, lc = lane & 3;

    int ar = tid >> 2, ak = (tid & 3) * 4;  // A: rows ar, ar+64; k cols ak..ak+3
    int br = tid >> 5, bc = (tid & 31) * 4; // B: rows br, br+8; n cols bc..bc+3

    float4 la[2], lb[2];
    float c[2][8][4];
    #pragma unroll
    for (int mi = 0; mi < 2; mi++)
        #pragma unroll
        for (int ni = 0; ni < 8; ni++)
            #pragma unroll
            for (int q = 0; q < 4; q++) c[mi][ni][q] = 0.f;

    // prologue loads
    #pragma unroll
    for (int i = 0; i < 2; i++) {
        int r = ar + i * 64;
        la[i] = make_float4(0.f, 0.f, 0.f, 0.f);
        if (row0 + r < M) la[i] = *(const float4*)(A + (size_t)(row0 + r) * K + ak);
        lb[i] = *(const float4*)(W + (size_t)(br + i * 8) * HD + col0 + bc);
    }
    #pragma unroll
    for (int i = 0; i < 2; i++) {
        int r = ar + i * 64;
        As[0][r][ak + 0] = f2tf32(la[i].x); As[0][r][ak + 1] = f2tf32(la[i].y);
        As[0][r][ak + 2] = f2tf32(la[i].z); As[0][r][ak + 3] = f2tf32(la[i].w);
        unsigned* bp = &Bs[0][br + i * 8][bc];
        bp[0] = f2tf32(lb[i].x); bp[1] = f2tf32(lb[i].y);
        bp[2] = f2tf32(lb[i].z); bp[3] = f2tf32(lb[i].w);
    }
    __syncthreads();

    int nk = K / 16;
    for (int kc = 0; kc < nk; kc++) {
        int buf = kc & 1;
        bool nxt = (kc + 1) < nk;
        if (nxt) {
            int kt = (kc + 1) * 16;
            #pragma unroll
            for (int i = 0; i < 2; i++) {
                int r = ar + i * 64;
                la[i] = make_float4(0.f, 0.f, 0.f, 0.f);
                if (row0 + r < M) la[i] = *(const float4*)(A + (size_t)(row0 + r) * K + kt + ak);
                lb[i] = *(const float4*)(W + (size_t)(kt + br + i * 8) * HD + col0 + bc);
            }
        }
        #pragma unroll
        for (int ks = 0; ks < 2; ks++) {
            int k = ks * 8;
            unsigned a[2][4], b[8][2];
            #pragma unroll
            for (int mi = 0; mi < 2; mi++) {
                int rb = wm * 32 + mi * 16 + gr;
                a[mi][0] = As[buf][rb][k + lc];
                a[mi][1] = As[buf][rb + 8][k + lc];
                a[mi][2] = As[buf][rb][k + lc + 4];
                a[mi][3] = As[buf][rb + 8][k + lc + 4];
            }
            #pragma unroll
            for (int ni = 0; ni < 8; ni++) {
                int cb = wn * 64 + ni * 8 + gr;
                b[ni][0] = Bs[buf][k + lc][cb];
                b[ni][1] = Bs[buf][k + lc + 4][cb];
            }
            #pragma unroll
            for (int mi = 0; mi < 2; mi++)
                #pragma unroll
                for (int ni = 0; ni < 8; ni++)
                    mma_tf32(c[mi][ni], a[mi], b[ni]);
        }
        if (nxt) {
            int nb = buf ^ 1;
            #pragma unroll
            for (int i = 0; i < 2; i++) {
                int r = ar + i * 64;
                As[nb][r][ak + 0] = f2tf32(la[i].x); As[nb][r][ak + 1] = f2tf32(la[i].y);
                As[nb][r][ak + 2] = f2tf32(la[i].z); As[nb][r][ak + 3] = f2tf32(la[i].w);
                unsigned* bp = &Bs[nb][br + i * 8][bc];
                bp[0] = f2tf32(lb[i].x); bp[1] = f2tf32(lb[i].y);
                bp[2] = f2tf32(lb[i].z); bp[3] = f2tf32(lb[i].w);
            }
        }
        __syncthreads();
    }

    // epilogue: add bias, store float2 per (c0,c1)/(c2,c3) pair
    #pragma unroll
    for (int mi = 0; mi < 2; mi++) {
        int r0 = row0 + wm * 32 + mi * 16 + gr;
        #pragma unroll
        for (int ni = 0; ni < 8; ni++) {
            int cl = col0 + wn * 64 + ni * 8 + lc * 2;
            float b0 = bptr[cl], b1 = bptr[cl + 1];
            if (r0 < M)
                *(float2*)(outp + (size_t)r0 * HD + cl) =
                    make_float2(c[mi][ni][0] + b0, c[mi][ni][1] + b1);
            if (r0 + 8 < M)
                *(float2*)(outp + (size_t)(r0 + 8) * HD + cl) =
                    make_float2(c[mi][ni][2] + b0, c[mi][ni][3] + b1);
        }
    }
}

// ---------------- CSR build: histogram, scan, scatter ----------------
__global__ void k_hist(const int* __restrict__ ecc_dst, const int* __restrict__ ecs_dst) {
    int gid = blockIdx.x * blockDim.x + threadIdx.x;
    if (gid < 9 * ECC) {
        int r = gid / ECC;
        atomicAdd(&g_cnt_cc[r * NC + ecc_dst[gid]], 1);
    } else if (gid < 9 * ECC + 3 * ECS) {
        int g = gid - 9 * ECC;
        int t = g / ECS;
        atomicAdd(&g_cnt_cs[t * NS + ecs_dst[g]], 1);
    }
}

__global__ void __launch_bounds__(1024) k_scan() {
    int rel = blockIdx.x;
    int n; int* cnt; int* off; int* cur;
    if (rel < 9) { n = NC; cnt = g_cnt_cc + rel * NC; off = g_off_cc + rel * NC; cur = g_cur_cc + rel * NC; }
    else { int t = rel - 9; n = NS; cnt = g_cnt_cs + t * NS; off = g_off_cs + t * NS; cur = g_cur_cs + t * NS; }
    int tid = threadIdx.x;
    int CH = (n + 1023) / 1024;
    int base = tid * CH;
    int loc[10]; int s = 0;
    for (int i = 0; i < CH; i++) {
        int v = (base + i < n) ? cnt[base + i] : 0;
        loc[i] = s; s += v;
    }
    __shared__ int sums[1024];
    sums[tid] = s; __syncthreads();
    for (int o = 1; o < 1024; o <<= 1) {
        int v = (tid >= o) ? sums[tid - o] : 0;
        __syncthreads();
        sums[tid] += v;
        __syncthreads();
    }
    int prefix = (tid == 0) ? 0 : sums[tid - 1];
    for (int i = 0; i < CH; i++) if (base + i < n) {
        int o2 = prefix + loc[i];
        off[base + i] = o2;
        cur[base + i] = o2;
    }
}

__global__ void k_scatter(const int* __restrict__ ecc_src, const int* __restrict__ ecc_dst,
                          const int* __restrict__ ecs_src, const int* __restrict__ ecs_dst) {
    int gid = blockIdx.x * blockDim.x + threadIdx.x;
    if (gid < 9 * ECC) {
        int r = gid / ECC;
        int pos = atomicAdd(&g_cur_cc[r * NC + ecc_dst[gid]], 1);
        g_csr_cc[r * ECC + pos] = ecc_src[gid];
    } else if (gid < 9 * ECC + 3 * ECS) {
        int g = gid - 9 * ECC;
        int t = g / ECS;
        int pos = atomicAdd(&g_cur_cs[t * NS + ecs_dst[g]], 1);
        g_csr_cs[t * ECS + pos] = ecs_src[g];
    }
}

// ---------------- edge softmax coefficients ----------------
__device__ __forceinline__ float lrelu(float x) { return x > 0.f ? x : LALPHA * x; }

__global__ void __launch_bounds__(256) k_coef() {
    int y = blockIdx.y;
    int warp = threadIdx.x >> 5, lane = threadIdx.x & 31;
    int node = blockIdx.x * 8 + warp;
    int n; const int* csr; const int* offp; const int* cntp;
    const float* asb; const float* adp; float* coef; float* invsp;
    if (y < 9) {
        n = NC; csr = g_csr_cc + (size_t)y * ECC;
        offp = g_off_cc + y * NC; cntp = g_cnt_cc + y * NC;
        asb = g_as_cc + (size_t)y * NC * H;
        adp = g_ad_cc + (size_t)y * NC * H;
        coef = g_coef_cc + (size_t)y * ECC * H;
        invsp = g_invs_cc + (size_t)y * NC * H;
    } else {
        int t = y - 9;
        n = NS; csr = g_csr_cs + (size_t)t * ECS;
        offp = g_off_cs + t * NS; cntp = g_cnt_cs + t * NS;
        asb = g_as_cs + (size_t)t * NC * H;
        adp = g_ad_s + (size_t)t * NS * H;
        coef = g_coef_cs + (size_t)t * ECS * H;
        invsp = g_invs_cs + (size_t)t * NS * H;
    }
    if (node >= n) return;
    int beg = offp[node], cnt = cntp[node];

    float ad[H];
    {
        float4 a0 = *(const float4*)(adp + (size_t)node * H);
        float4 a1 = *(const float4*)(adp + (size_t)node * H + 4);
        ad[0]=a0.x; ad[1]=a0.y; ad[2]=a0.z; ad[3]=a0.w;
        ad[4]=a1.x; ad[5]=a1.y; ad[6]=a1.z; ad[7]=a1.w;
    }

    float m[H];
    #pragma unroll
    for (int h = 0; h < H; h++) m[h] = NEG_BIG;
    float evr[2][H];
    int myCnt = 0;
    for (int e = lane; e < cnt; e += 32) {
        int src = __ldg(&csr[beg + e]);
        float4 s0 = *(const float4*)(asb + (size_t)src * H);
        float4 s1 = *(const float4*)(asb + (size_t)src * H + 4);
        float ev[H];
        ev[0]=lrelu(s0.x+ad[0]); ev[1]=lrelu(s0.y+ad[1]); ev[2]=lrelu(s0.z+ad[2]); ev[3]=lrelu(s0.w+ad[3]);
        ev[4]=lrelu(s1.x+ad[4]); ev[5]=lrelu(s1.y+ad[5]); ev[6]=lrelu(s1.z+ad[6]); ev[7]=lrelu(s1.w+ad[7]);
        if (myCnt < 2) {
            #pragma unroll
            for (int h = 0; h < H; h++) evr[myCnt][h] = ev[h];
        }
        #pragma unroll
        for (int h = 0; h < H; h++) m[h] = fmaxf(m[h], ev[h]);
        myCnt++;
    }
    #pragma unroll
    for (int h = 0; h < H; h++) {
        #pragma unroll
        for (int o = 16; o > 0; o >>= 1) m[h] = fmaxf(m[h], __shfl_xor_sync(0xffffffffu, m[h], o));
    }
    float sum[H];
    #pragma unroll
    for (int h = 0; h < H; h++) sum[h] = 0.f;
    int idx = 0;
    for (int e = lane; e < cnt; e += 32) {
        float ev[H];
        if (idx < 2) {
            #pragma unroll
            for (int h = 0; h < H; h++) ev[h] = evr[idx][h];
        } else {
            int src = __ldg(&csr[beg + e]);
            float4 s0 = *(const float4*)(asb + (size_t)src * H);
            float4 s1 = *(const float4*)(asb + (size_t)src * H + 4);
            ev[0]=lrelu(s0.x+ad[0]); ev[1]=lrelu(s0.y+ad[1]); ev[2]=lrelu(s0.z+ad[2]); ev[3]=lrelu(s0.w+ad[3]);
            ev[4]=lrelu(s1.x+ad[4]); ev[5]=lrelu(s1.y+ad[5]); ev[6]=lrelu(s1.z+ad[6]); ev[7]=lrelu(s1.w+ad[7]);
        }
        float p[H];
        #pragma unroll
        for (int h = 0; h < H; h++) { p[h] = __expf(ev[h] - m[h]); sum[h] += p[h]; }
        float* cp = coef + (size_t)(beg + e) * H;
        float4 c0, c1;
        c0.x=p[0]; c0.y=p[1]; c0.z=p[2]; c0.w=p[3];
        c1.x=p[4]; c1.y=p[5]; c1.z=p[6]; c1.w=p[7];
        *(float4*)cp = c0; *(float4*)(cp + 4) = c1;
        idx++;
    }
    #pragma unroll
    for (int h = 0; h < H; h++) {
        #pragma unroll
        for (int o = 16; o > 0; o >>= 1) sum[h] += __shfl_xor_sync(0xffffffffu, sum[h], o);
    }
    if (lane == 0) {
        float iv[H];
        #pragma unroll
        for (int h = 0; h < H; h++) iv[h] = (cnt > 0) ? 1.f / sum[h] : 0.f;
        float* op = invsp + (size_t)node * H;
        float4 v0, v1;
        v0.x=iv[0]; v0.y=iv[1]; v0.z=iv[2]; v0.w=iv[3];
        v1.x=iv[4]; v1.y=iv[5]; v1.z=iv[6]; v1.w=iv[7];
        *(float4*)op = v0; *(float4*)(op + 4) = v1;
    }
}

// ---------------- weighted gather: lane owns 8 contiguous channels ----------------
__global__ void __launch_bounds__(256) k_gather_cc(float* __restrict__ out) {
    int dt = blockIdx.y;
    int warp = threadIdx.x >> 5, lane = threadIdx.x & 31;
    int node = blockIdx.x * 8 + warp;
    if (node >= NC) return;
    int hq = lane >> 2;

    float outacc[8] = {};
    #pragma unroll 1
    for (int s = 0; s < 3; s++) {
        int r = 3 * s + dt;
        int beg = g_off_cc[r * NC + node];
        int cnt = g_cnt_cc[r * NC + node];
        if (cnt == 0) continue;
        float invs = g_invs_cc[((size_t)r * NC + node) * H + hq];
        const float* Wh = g_Wh_cc + (size_t)r * NC * HD;
        const int* csr = g_csr_cc + (size_t)r * ECC;
        const float* coef = g_coef_cc + (size_t)r * ECC * H;
        float acc[8] = {};
        #pragma unroll 4
        for (int e = 0; e < cnt; e++) {
            int src = __ldg(&csr[beg + e]);
            float cf = __ldg(&coef[(size_t)(beg + e) * H + hq]);
            const float* wr = Wh + (size_t)src * HD + lane * 8;
            float4 w0 = *(const float4*)wr;
            float4 w1 = *(const float4*)(wr + 4);
            acc[0] += cf * w0.x; acc[1] += cf * w0.y; acc[2] += cf * w0.z; acc[3] += cf * w0.w;
            acc[4] += cf * w1.x; acc[5] += cf * w1.y; acc[6] += cf * w1.z; acc[7] += cf * w1.w;
        }
        #pragma unroll
        for (int j = 0; j < 8; j++) outacc[j] += acc[j] * invs;
    }
    float* o = out + ((size_t)dt * NC + node) * HD + lane * 8;
    float4 v0, v1;
    v0.x = fmaxf(outacc[0], 0.f); v0.y = fmaxf(outacc[1], 0.f);
    v0.z = fmaxf(outacc[2], 0.f); v0.w = fmaxf(outacc[3], 0.f);
    v1.x = fmaxf(outacc[4], 0.f); v1.y = fmaxf(outacc[5], 0.f);
    v1.z = fmaxf(outacc[6], 0.f); v1.w = fmaxf(outacc[7], 0.f);
    *(float4*)o = v0; *(float4*)(o + 4) = v1;
}

__global__ void __launch_bounds__(256) k_gather_state(float* __restrict__ out) {
    int warp = threadIdx.x >> 5, lane = threadIdx.x & 31;
    int node = blockIdx.x * 8 + warp;
    if (node >= NS) return;
    int hq = lane >> 2;

    float outacc[8];
    {
        const float* sp = g_Wh_in + (size_t)node * HD + lane * 8;
        float4 s0 = *(const float4*)sp;
        float4 s1 = *(const float4*)(sp + 4);
        outacc[0]=s0.x; outacc[1]=s0.y; outacc[2]=s0.z; outacc[3]=s0.w;
        outacc[4]=s1.x; outacc[5]=s1.y; outacc[6]=s1.z; outacc[7]=s1.w;
    }
    #pragma unroll 1
    for (int t = 0; t < 3; t++) {
        int beg = g_off_cs[t * NS + node];
        int cnt = g_cnt_cs[t * NS + node];
        if (cnt == 0) continue;
        float invs = g_invs_cs[((size_t)t * NS + node) * H + hq];
        const float* Wh = g_Wh_cs + (size_t)t * NC * HD;
        const int* csr = g_csr_cs + (size_t)t * ECS;
        const float* coef = g_coef_cs + (size_t)t * ECS * H;
        float acc[8] = {};
        #pragma unroll 4
        for (int e = 0; e < cnt; e++) {
            int src = __ldg(&csr[beg + e]);
            float cf = __ldg(&coef[(size_t)(beg + e) * H + hq]);
            const float* wr = Wh + (size_t)src * HD + lane * 8;
            float4 w0 = *(const float4*)wr;
            float4 w1 = *(const float4*)(wr + 4);
            acc[0] += cf * w0.x; acc[1] += cf * w0.y; acc[2] += cf * w0.z; acc[3] += cf * w0.w;
            acc[4] += cf * w1.x; acc[5] += cf * w1.y; acc[6] += cf * w1.z; acc[7] += cf * w1.w;
        }
        #pragma unroll
        for (int j = 0; j < 8; j++) outacc[j] += acc[j] * invs;
    }
    float* o = out + (size_t)3 * NC * HD + (size_t)node * HD + lane * 8;
    float4 v0, v1;
    v0.x = fmaxf(outacc[0], 0.f); v0.y = fmaxf(outacc[1], 0.f);
    v0.z = fmaxf(outacc[2], 0.f); v0.w = fmaxf(outacc[3], 0.f);
    v1.x = fmaxf(outacc[4], 0.f); v1.y = fmaxf(outacc[5], 0.f);
    v1.z = fmaxf(outacc[6], 0.f); v1.w = fmaxf(outacc[7], 0.f);
    *(float4*)o = v0; *(float4*)(o + 4) = v1;
}

// ---------------- launch ----------------
extern "C" void kernel_launch(void* const* d_in, const int* in_sizes, int n_in,
                              void* d_out, int out_size) {
    const float* f1      = (const float*)d_in[0];
    const float* f2      = (const float*)d_in[1];
    const float* f3      = (const float*)d_in[2];
    const float* fs      = (const float*)d_in[3];
    const float* W_node  = (const float*)d_in[4];
    const float* b_node  = (const float*)d_in[5];
    const float* W_cc    = (const float*)d_in[6];
    const float* b_cc    = (const float*)d_in[7];
    const float* W_cs    = (const float*)d_in[8];
    const float* b_cs    = (const float*)d_in[9];
    const float* W_in    = (const float*)d_in[10];
    const float* b_in    = (const float*)d_in[11];
    const float* attn_cc = (const float*)d_in[12];
    const float* attn_cs = (const float*)d_in[13];
    const int* ecc_src   = (const int*)d_in[14];
    const int* ecc_dst   = (const int*)d_in[15];
    const int* ecs_src   = (const int*)d_in[16];
    const int* ecs_dst   = (const int*)d_in[17];
    float* out = (float*)d_out;

    k_zero_counters<<<(9 * NC + 255) / 256, 256>>>();
    k_wred<<<(24 * INC * H + 255) / 256, 256>>>(W_node, b_node, W_cc, b_cc, W_cs, b_cs, W_in, b_in, attn_cc, attn_cs);
    k_skinny<<<dim3(1250, 24), 256>>>(f1, f2, f3, fs);
    int tot = 9 * ECC + 3 * ECS;
    k_hist<<<(tot + 255) / 256, 256>>>(ecc_dst, ecs_dst);
    k_scan<<<12, 1024>>>();
    k_scatter<<<(tot + 255) / 256, 256>>>(ecc_src, ecc_dst, ecs_src, ecs_dst);
    k_coef<<<dim3(1250, 12), 256>>>();
    k_gemm<<<dim3(79, 2, 13), 256>>>(f1, f2, f3, fs, W_cc, b_cc, W_cs, b_cs, W_in, b_in);
    k_gather_cc<<<dim3(1250, 3), 256>>>(out);
    k_gather_state<<<128, 256>>>(out);
}

// round 5
// speedup vs baseline: 1.5714x; 1.0195x over previous
#include <cuda_runtime.h>
#include <cuda_fp16.h>
#include <cstdint>

#define H   8
#define Dd  32
#define HD  256
#define NC  10000
#define NS  1024
#define INC 128
#define INS 64
#define ECC 120000
#define ECS 10000
#define LALPHA 0.2f
#define NEG_BIG -1e30f

// ---------------- device scratch (static; no runtime allocation) ----------------
__device__ __half g_Wh_cc[9u * NC * HD];     // 46 MB (fp16)
__device__ __half g_Wh_cs[3u * NC * HD];     // 15 MB
__device__ __half g_Wh_in[NS * HD];

__device__ float g_as_cc[9 * NC * H];
__device__ float g_ad_cc[9 * NC * H];
__device__ float g_as_cs[3 * NC * H];
__device__ float g_ad_s[3 * NS * H];

__device__ float g_coef_cc[(size_t)9 * ECC * H];   // unnormalized softmax numerators
__device__ float g_coef_cs[(size_t)3 * ECS * H];
__device__ float g_invs_cc[9 * NC * H];            // 1/sum per (rel,node,h)
__device__ float g_invs_cs[3 * NS * H];

__device__ float g_wred_as[9 * INC * H];
__device__ float g_wred_ad[9 * INC * H];
__device__ float g_wred_as_cs[3 * INC * H];
__device__ float g_wred_ad_s[3 * INS * H];
__device__ float g_bred_as[9 * H];
__device__ float g_bred_ad[9 * H];
__device__ float g_bred_as_cs[3 * H];
__device__ float g_bred_ad_s[3 * H];

__device__ int g_cnt_cc[9 * NC];
__device__ int g_off_cc[9 * NC];
__device__ int g_cur_cc[9 * NC];
__device__ int g_csr_cc[9 * ECC];
__device__ int g_cnt_cs[3 * NS];
__device__ int g_off_cs[3 * NS];
__device__ int g_cur_cs[3 * NS];
__device__ int g_csr_cs[3 * ECS];

// ---------------- zero counters ----------------
__global__ void k_zero_counters() {
    int i = blockIdx.x * blockDim.x + threadIdx.x;
    if (i < 9 * NC) g_cnt_cc[i] = 0;
    if (i < 3 * NS) g_cnt_cs[i] = 0;
}

// ---------------- reduce attention vectors into weights ----------------
__global__ void k_wred(const float* __restrict__ W_node, const float* __restrict__ b_node,
                       const float* __restrict__ W_cc,   const float* __restrict__ b_cc,
                       const float* __restrict__ W_cs,   const float* __restrict__ b_cs,
                       const float* __restrict__ W_in,   const float* __restrict__ b_in,
                       const float* __restrict__ attn_cc, const float* __restrict__ attn_cs) {
    int gid = blockIdx.x * blockDim.x + threadIdx.x;
    if (gid >= 24 * INC * H) return;
    int j   = gid / (INC * H);
    int rem = gid % (INC * H);
    int k = rem / H, h = rem % H;
    const float *Wsrc, *att, *bvec;
    float *dst, *bdst;
    int Kin = INC;
    if (j < 9) {
        Wsrc = W_cc + (size_t)j * INC * HD;
        att  = attn_cc + (size_t)(j * 2 + 0) * HD;
        bvec = b_cc + (size_t)j * HD;
        dst  = g_wred_as + j * INC * H; bdst = g_bred_as + j * H;
    } else if (j < 18) {
        int r = j - 9;
        Wsrc = W_node + (size_t)(r % 3) * INC * HD;
        att  = attn_cc + (size_t)(r * 2 + 1) * HD;
        bvec = b_node + (size_t)(r % 3) * HD;
        dst  = g_wred_ad + r * INC * H; bdst = g_bred_ad + r * H;
    } else if (j < 21) {
        int t = j - 18;
        Wsrc = W_cs + (size_t)t * INC * HD;
        att  = attn_cs + (size_t)(t * 2 + 0) * HD;
        bvec = b_cs + (size_t)t * HD;
        dst  = g_wred_as_cs + t * INC * H; bdst = g_bred_as_cs + t * H;
    } else {
        int t = j - 21;
        Wsrc = W_in;
        att  = attn_cs + (size_t)(t * 2 + 1) * HD;
        bvec = b_in;
        dst  = g_wred_ad_s + t * INS * H; bdst = g_bred_ad_s + t * H;
        Kin = INS;
    }
    if (k >= Kin) return;
    float s = 0.f;
    #pragma unroll
    for (int d = 0; d < Dd; d++)
        s += Wsrc[(size_t)k * HD + h * Dd + d] * att[h * Dd + d];
    dst[k * H + h] = s;
    if (k == 0) {
        float bs = 0.f;
        #pragma unroll
        for (int d = 0; d < Dd; d++) bs += bvec[h * Dd + d] * att[h * Dd + d];
        bdst[h] = bs;
    }
}

// ---------------- fused skinny GEMMs: one pass over each node type ----------
// For C type t (y=0..2): 7 groups — as_cc[t*3+d] d=0..2, ad_cc[s*3+t] s=0..2, as_cs[t]
// For state (y=3): 3 groups — ad_s[t] t=0..2 (Kin=64)
__global__ void __launch_bounds__(256) k_skinny(const float* __restrict__ f1,
                                                const float* __restrict__ f2,
                                                const float* __restrict__ f3,
                                                const float* __restrict__ fs) {
    int t = blockIdx.y;
    __shared__ float Ws[7][H][INC];
    __shared__ float bsm[7][H];
    __shared__ const float* wptr[7];
    __shared__ float* optr[7];
    __shared__ const float* bptr[7];

    int Kin = (t < 3) ? INC : INS;
    int nG  = (t < 3) ? 7 : 3;
    int nNodes = (t < 3) ? NC : NS;
    const float* feat = (t == 0) ? f1 : (t == 1) ? f2 : (t == 2) ? f3 : fs;

    if (threadIdx.x < (unsigned)nG) {
        int g = threadIdx.x;
        if (t < 3) {
            if (g < 3) {            // as_cc, rel r = t*3+g
                int r = t * 3 + g;
                wptr[g] = g_wred_as + r * INC * H;
                bptr[g] = g_bred_as + r * H;
                optr[g] = g_as_cc + (size_t)r * NC * H;
            } else if (g < 6) {     // ad_cc, rel r = (g-3)*3+t
                int r = (g - 3) * 3 + t;
                wptr[g] = g_wred_ad + r * INC * H;
                bptr[g] = g_bred_ad + r * H;
                optr[g] = g_ad_cc + (size_t)r * NC * H;
            } else {                // as_cs[t]
                wptr[g] = g_wred_as_cs + t * INC * H;
                bptr[g] = g_bred_as_cs + t * H;
                optr[g] = g_as_cs + (size_t)t * NC * H;
            }
        } else {                    // state: ad_s[g]
            wptr[g] = g_wred_ad_s + g * INS * H;
            bptr[g] = g_bred_ad_s + g * H;
            optr[g] = g_ad_s + (size_t)g * NS * H;
        }
    }
    __syncthreads();

    for (int idx = threadIdx.x; idx < nG * H * Kin; idx += 256) {
        int g = idx / (H * Kin);
        int rem = idx % (H * Kin);
        int h = rem / Kin, k = rem % Kin;
        Ws[g][h][k] = wptr[g][k * H + h];
    }
    if (threadIdx.x < (unsigned)(nG * H)) {
        int g = threadIdx.x / H, h = threadIdx.x % H;
        bsm[g][h] = bptr[g][h];
    }
    __syncthreads();

    int warp = threadIdx.x >> 5, lane = threadIdx.x & 31;
    int node = blockIdx.x * 8 + warp;
    if (node >= nNodes) return;
    const float* frow = feat + (size_t)node * Kin;
    float f[4];
    int nc = Kin / 32;
    for (int c = 0; c < nc; c++) f[c] = frow[c * 32 + lane];

    for (int g = 0; g < nG; g++) {
        float mine = 0.f;
        #pragma unroll
        for (int h = 0; h < H; h++) {
            float v = 0.f;
            for (int c = 0; c < nc; c++) v += f[c] * Ws[g][h][c * 32 + lane];
            #pragma unroll
            for (int o = 16; o > 0; o >>= 1) v += __shfl_xor_sync(0xffffffffu, v, o);
            if (lane == h) mine = v;
        }
        if (lane < H) optr[g][(size_t)node * H + lane] = mine + bsm[g][lane];
    }
}

// ---------------- TF32 tensor-core GEMM helpers ----------------
__device__ __forceinline__ unsigned f2tf32(float x) {
    unsigned u; asm("cvt.rna.tf32.f32 %0, %1;" : "=r"(u) : "f"(x)); return u;
}
__device__ __forceinline__ void mma_tf32(float c[4], const unsigned a[4], const unsigned b[2]) {
    asm volatile("mma.sync.aligned.m16n8k8.row.col.f32.tf32.tf32.f32 "
        "{%0,%1,%2,%3}, {%4,%5,%6,%7}, {%8,%9}, {%0,%1,%2,%3};"
        : "+f"(c[0]), "+f"(c[1]), "+f"(c[2]), "+f"(c[3])
        : "r"(a[0]), "r"(a[1]), "r"(a[2]), "r"(a[3]), "r"(b[0]), "r"(b[1]));
}

// ---------------- big GEMMs: 13 jobs, TF32 MMA, fp16 output ----------------
__global__ void __launch_bounds__(256, 2) k_gemm(const float* __restrict__ f1, const float* __restrict__ f2,
                                                 const float* __restrict__ f3, const float* __restrict__ fs,
                                                 const float* __restrict__ Wcc, const float* __restrict__ bcc,
                                                 const float* __restrict__ Wcs, const float* __restrict__ bcs,
                                                 const float* __restrict__ Win, const float* __restrict__ bin) {
    int z = blockIdx.z;
    const float* A; const float* W; const float* bptr; __half* outp; int M, K;
    if (z < 9) {
        int s = z / 3;
        A = (s == 0) ? f1 : (s == 1) ? f2 : f3;
        W = Wcc + (size_t)z * INC * HD; bptr = bcc + (size_t)z * HD;
        outp = g_Wh_cc + (size_t)z * NC * HD; M = NC; K = INC;
    } else if (z < 12) {
        int t = z - 9;
        A = (t == 0) ? f1 : (t == 1) ? f2 : f3;
        W = Wcs + (size_t)t * INC * HD; bptr = bcs + (size_t)t * HD;
        outp = g_Wh_cs + (size_t)t * NC * HD; M = NC; K = INC;
    } else {
        A = fs; W = Win; bptr = bin; outp = g_Wh_in; M = NS; K = INS;
    }
    int row0 = blockIdx.x * 128;
    if (row0 >= M) return;
    int col0 = blockIdx.y * 128;

    __shared__ unsigned As[2][128][20];
    __shared__ unsigned Bs[2][16][132];

    int tid = threadIdx.x;
    int warp = tid >> 5, lane = tid & 31;
    int wm = warp & 3, wn = warp >> 2;
    int gr = lane >> 2, lc = lane & 3;

    int ar = tid >> 2, ak = (tid & 3) * 4;
    int br = tid >> 5, bc = (tid & 31) * 4;

    float4 la[2], lb[2];
    float c[2][8][4];
    #pragma unroll
    for (int mi = 0; mi < 2; mi++)
        #pragma unroll
        for (int ni = 0; ni < 8; ni++)
            #pragma unroll
            for (int q = 0; q < 4; q++) c[mi][ni][q] = 0.f;

    #pragma unroll
    for (int i = 0; i < 2; i++) {
        int r = ar + i * 64;
        la[i] = make_float4(0.f, 0.f, 0.f, 0.f);
        if (row0 + r < M) la[i] = *(const float4*)(A + (size_t)(row0 + r) * K + ak);
        lb[i] = *(const float4*)(W + (size_t)(br + i * 8) * HD + col0 + bc);
    }
    #pragma unroll
    for (int i = 0; i < 2; i++) {
        int r = ar + i * 64;
        As[0][r][ak + 0] = f2tf32(la[i].x); As[0][r][ak + 1] = f2tf32(la[i].y);
        As[0][r][ak + 2] = f2tf32(la[i].z); As[0][r][ak + 3] = f2tf32(la[i].w);
        unsigned* bp = &Bs[0][br + i * 8][bc];
        bp[0] = f2tf32(lb[i].x); bp[1] = f2tf32(lb[i].y);
        bp[2] = f2tf32(lb[i].z); bp[3] = f2tf32(lb[i].w);
    }
    __syncthreads();

    int nk = K / 16;
    for (int kc = 0; kc < nk; kc++) {
        int buf = kc & 1;
        bool nxt = (kc + 1) < nk;
        if (nxt) {
            int kt = (kc + 1) * 16;
            #pragma unroll
            for (int i = 0; i < 2; i++) {
                int r = ar + i * 64;
                la[i] = make_float4(0.f, 0.f, 0.f, 0.f);
                if (row0 + r < M) la[i] = *(const float4*)(A + (size_t)(row0 + r) * K + kt + ak);
                lb[i] = *(const float4*)(W + (size_t)(kt + br + i * 8) * HD + col0 + bc);
            }
        }
        #pragma unroll
        for (int ks = 0; ks < 2; ks++) {
            int k = ks * 8;
            unsigned a[2][4], b[8][2];
            #pragma unroll
            for (int mi = 0; mi < 2; mi++) {
                int rb = wm * 32 + mi * 16 + gr;
                a[mi][0] = As[buf][rb][k + lc];
                a[mi][1] = As[buf][rb + 8][k + lc];
                a[mi][2] = As[buf][rb][k + lc + 4];
                a[mi][3] = As[buf][rb + 8][k + lc + 4];
            }
            #pragma unroll
            for (int ni = 0; ni < 8; ni++) {
                int cb = wn * 64 + ni * 8 + gr;
                b[ni][0] = Bs[buf][k + lc][cb];
                b[ni][1] = Bs[buf][k + lc + 4][cb];
            }
            #pragma unroll
            for (int mi = 0; mi < 2; mi++)
                #pragma unroll
                for (int ni = 0; ni < 8; ni++)
                    mma_tf32(c[mi][ni], a[mi], b[ni]);
        }
        if (nxt) {
            int nb = buf ^ 1;
            #pragma unroll
            for (int i = 0; i < 2; i++) {
                int r = ar + i * 64;
                As[nb][r][ak + 0] = f2tf32(la[i].x); As[nb][r][ak + 1] = f2tf32(la[i].y);
                As[nb][r][ak + 2] = f2tf32(la[i].z); As[nb][r][ak + 3] = f2tf32(la[i].w);
                unsigned* bp = &Bs[nb][br + i * 8][bc];
                bp[0] = f2tf32(lb[i].x); bp[1] = f2tf32(lb[i].y);
                bp[2] = f2tf32(lb[i].z); bp[3] = f2tf32(lb[i].w);
            }
        }
        __syncthreads();
    }

    #pragma unroll
    for (int mi = 0; mi < 2; mi++) {
        int r0 = row0 + wm * 32 + mi * 16 + gr;
        #pragma unroll
        for (int ni = 0; ni < 8; ni++) {
            int cl = col0 + wn * 64 + ni * 8 + lc * 2;
            float b0 = bptr[cl], b1 = bptr[cl + 1];
            if (r0 < M)
                *(__half2*)(outp + (size_t)r0 * HD + cl) =
                    __floats2half2_rn(c[mi][ni][0] + b0, c[mi][ni][1] + b1);
            if (r0 + 8 < M)
                *(__half2*)(outp + (size_t)(r0 + 8) * HD + cl) =
                    __floats2half2_rn(c[mi][ni][2] + b0, c[mi][ni][3] + b1);
        }
    }
}

// ---------------- CSR build: histogram, scan, scatter ----------------
__global__ void k_hist(const int* __restrict__ ecc_dst, const int* __restrict__ ecs_dst) {
    int gid = blockIdx.x * blockDim.x + threadIdx.x;
    if (gid < 9 * ECC) {
        int r = gid / ECC;
        atomicAdd(&g_cnt_cc[r * NC + ecc_dst[gid]], 1);
    } else if (gid < 9 * ECC + 3 * ECS) {
        int g = gid - 9 * ECC;
        int t = g / ECS;
        atomicAdd(&g_cnt_cs[t * NS + ecs_dst[g]], 1);
    }
}

__global__ void __launch_bounds__(1024) k_scan() {
    int rel = blockIdx.x;
    int n; int* cnt; int* off; int* cur;
    if (rel < 9) { n = NC; cnt = g_cnt_cc + rel * NC; off = g_off_cc + rel * NC; cur = g_cur_cc + rel * NC; }
    else { int t = rel - 9; n = NS; cnt = g_cnt_cs + t * NS; off = g_off_cs + t * NS; cur = g_cur_cs + t * NS; }
    int tid = threadIdx.x;
    int CH = (n + 1023) / 1024;
    int base = tid * CH;
    int loc[10]; int s = 0;
    for (int i = 0; i < CH; i++) {
        int v = (base + i < n) ? cnt[base + i] : 0;
        loc[i] = s; s += v;
    }
    __shared__ int sums[1024];
    sums[tid] = s; __syncthreads();
    for (int o = 1; o < 1024; o <<= 1) {
        int v = (tid >= o) ? sums[tid - o] : 0;
        __syncthreads();
        sums[tid] += v;
        __syncthreads();
    }
    int prefix = (tid == 0) ? 0 : sums[tid - 1];
    for (int i = 0; i < CH; i++) if (base + i < n) {
        int o2 = prefix + loc[i];
        off[base + i] = o2;
        cur[base + i] = o2;
    }
}

__global__ void k_scatter(const int* __restrict__ ecc_src, const int* __restrict__ ecc_dst,
                          const int* __restrict__ ecs_src, const int* __restrict__ ecs_dst) {
    int gid = blockIdx.x * blockDim.x + threadIdx.x;
    if (gid < 9 * ECC) {
        int r = gid / ECC;
        int pos = atomicAdd(&g_cur_cc[r * NC + ecc_dst[gid]], 1);
        g_csr_cc[r * ECC + pos] = ecc_src[gid];
    } else if (gid < 9 * ECC + 3 * ECS) {
        int g = gid - 9 * ECC;
        int t = g / ECS;
        int pos = atomicAdd(&g_cur_cs[t * NS + ecs_dst[g]], 1);
        g_csr_cs[t * ECS + pos] = ecs_src[g];
    }
}

// ---------------- edge softmax coefficients ----------------
__device__ __forceinline__ float lrelu(float x) { return x > 0.f ? x : LALPHA * x; }

__global__ void __launch_bounds__(256) k_coef() {
    int y = blockIdx.y;
    int warp = threadIdx.x >> 5, lane = threadIdx.x & 31;
    int node = blockIdx.x * 8 + warp;
    int n; const int* csr; const int* offp; const int* cntp;
    const float* asb; const float* adp; float* coef; float* invsp;
    if (y < 9) {
        n = NC; csr = g_csr_cc + (size_t)y * ECC;
        offp = g_off_cc + y * NC; cntp = g_cnt_cc + y * NC;
        asb = g_as_cc + (size_t)y * NC * H;
        adp = g_ad_cc + (size_t)y * NC * H;
        coef = g_coef_cc + (size_t)y * ECC * H;
        invsp = g_invs_cc + (size_t)y * NC * H;
    } else {
        int t = y - 9;
        n = NS; csr = g_csr_cs + (size_t)t * ECS;
        offp = g_off_cs + t * NS; cntp = g_cnt_cs + t * NS;
        asb = g_as_cs + (size_t)t * NC * H;
        adp = g_ad_s + (size_t)t * NS * H;
        coef = g_coef_cs + (size_t)t * ECS * H;
        invsp = g_invs_cs + (size_t)t * NS * H;
    }
    if (node >= n) return;
    int beg = offp[node], cnt = cntp[node];

    float ad[H];
    {
        float4 a0 = *(const float4*)(adp + (size_t)node * H);
        float4 a1 = *(const float4*)(adp + (size_t)node * H + 4);
        ad[0]=a0.x; ad[1]=a0.y; ad[2]=a0.z; ad[3]=a0.w;
        ad[4]=a1.x; ad[5]=a1.y; ad[6]=a1.z; ad[7]=a1.w;
    }

    float m[H];
    #pragma unroll
    for (int h = 0; h < H; h++) m[h] = NEG_BIG;
    float evr[2][H];
    int myCnt = 0;
    for (int e = lane; e < cnt; e += 32) {
        int src = __ldg(&csr[beg + e]);
        float4 s0 = *(const float4*)(asb + (size_t)src * H);
        float4 s1 = *(const float4*)(asb + (size_t)src * H + 4);
        float ev[H];
        ev[0]=lrelu(s0.x+ad[0]); ev[1]=lrelu(s0.y+ad[1]); ev[2]=lrelu(s0.z+ad[2]); ev[3]=lrelu(s0.w+ad[3]);
        ev[4]=lrelu(s1.x+ad[4]); ev[5]=lrelu(s1.y+ad[5]); ev[6]=lrelu(s1.z+ad[6]); ev[7]=lrelu(s1.w+ad[7]);
        if (myCnt < 2) {
            #pragma unroll
            for (int h = 0; h < H; h++) evr[myCnt][h] = ev[h];
        }
        #pragma unroll
        for (int h = 0; h < H; h++) m[h] = fmaxf(m[h], ev[h]);
        myCnt++;
    }
    #pragma unroll
    for (int h = 0; h < H; h++) {
        #pragma unroll
        for (int o = 16; o > 0; o >>= 1) m[h] = fmaxf(m[h], __shfl_xor_sync(0xffffffffu, m[h], o));
    }
    float sum[H];
    #pragma unroll
    for (int h = 0; h < H; h++) sum[h] = 0.f;
    int idx = 0;
    for (int e = lane; e < cnt; e += 32) {
        float ev[H];
        if (idx < 2) {
            #pragma unroll
            for (int h = 0; h < H; h++) ev[h] = evr[idx][h];
        } else {
            int src = __ldg(&csr[beg + e]);
            float4 s0 = *(const float4*)(asb + (size_t)src * H);
            float4 s1 = *(const float4*)(asb + (size_t)src * H + 4);
            ev[0]=lrelu(s0.x+ad[0]); ev[1]=lrelu(s0.y+ad[1]); ev[2]=lrelu(s0.z+ad[2]); ev[3]=lrelu(s0.w+ad[3]);
            ev[4]=lrelu(s1.x+ad[4]); ev[5]=lrelu(s1.y+ad[5]); ev[6]=lrelu(s1.z+ad[6]); ev[7]=lrelu(s1.w+ad[7]);
        }
        float p[H];
        #pragma unroll
        for (int h = 0; h < H; h++) { p[h] = __expf(ev[h] - m[h]); sum[h] += p[h]; }
        float* cp = coef + (size_t)(beg + e) * H;
        float4 c0, c1;
        c0.x=p[0]; c0.y=p[1]; c0.z=p[2]; c0.w=p[3];
        c1.x=p[4]; c1.y=p[5]; c1.z=p[6]; c1.w=p[7];
        *(float4*)cp = c0; *(float4*)(cp + 4) = c1;
        idx++;
    }
    #pragma unroll
    for (int h = 0; h < H; h++) {
        #pragma unroll
        for (int o = 16; o > 0; o >>= 1) sum[h] += __shfl_xor_sync(0xffffffffu, sum[h], o);
    }
    if (lane == 0) {
        float iv[H];
        #pragma unroll
        for (int h = 0; h < H; h++) iv[h] = (cnt > 0) ? 1.f / sum[h] : 0.f;
        float* op = invsp + (size_t)node * H;
        float4 v0, v1;
        v0.x=iv[0]; v0.y=iv[1]; v0.z=iv[2]; v0.w=iv[3];
        v1.x=iv[4]; v1.y=iv[5]; v1.z=iv[6]; v1.w=iv[7];
        *(float4*)op = v0; *(float4*)(op + 4) = v1;
    }
}

// ---------------- weighted gather (fp16 messages): lane owns 8 channels ----------
__device__ __forceinline__ void acc_half8(float acc[8], float cf, const __half* wr) {
    uint4 u = *(const uint4*)wr;
    __half2 h0 = *(__half2*)&u.x, h1 = *(__half2*)&u.y;
    __half2 h2 = *(__half2*)&u.z, h3 = *(__half2*)&u.w;
    float2 f0 = __half22float2(h0), f1 = __half22float2(h1);
    float2 f2 = __half22float2(h2), f3 = __half22float2(h3);
    acc[0] += cf * f0.x; acc[1] += cf * f0.y;
    acc[2] += cf * f1.x; acc[3] += cf * f1.y;
    acc[4] += cf * f2.x; acc[5] += cf * f2.y;
    acc[6] += cf * f3.x; acc[7] += cf * f3.y;
}

__global__ void __launch_bounds__(256) k_gather_cc(float* __restrict__ out) {
    int dt = blockIdx.y;
    int warp = threadIdx.x >> 5, lane = threadIdx.x & 31;
    int node = blockIdx.x * 8 + warp;
    if (node >= NC) return;
    int hq = lane >> 2;

    float outacc[8] = {};
    #pragma unroll 1
    for (int s = 0; s < 3; s++) {
        int r = 3 * s + dt;
        int beg = g_off_cc[r * NC + node];
        int cnt = g_cnt_cc[r * NC + node];
        if (cnt == 0) continue;
        float invs = g_invs_cc[((size_t)r * NC + node) * H + hq];
        const __half* Wh = g_Wh_cc + (size_t)r * NC * HD;
        const int* csr = g_csr_cc + (size_t)r * ECC;
        const float* coef = g_coef_cc + (size_t)r * ECC * H;
        float acc[8] = {};
        #pragma unroll 4
        for (int e = 0; e < cnt; e++) {
            int src = __ldg(&csr[beg + e]);
            float cf = __ldg(&coef[(size_t)(beg + e) * H + hq]);
            acc_half8(acc, cf, Wh + (size_t)src * HD + lane * 8);
        }
        #pragma unroll
        for (int j = 0; j < 8; j++) outacc[j] += acc[j] * invs;
    }
    float* o = out + ((size_t)dt * NC + node) * HD + lane * 8;
    float4 v0, v1;
    v0.x = fmaxf(outacc[0], 0.f); v0.y = fmaxf(outacc[1], 0.f);
    v0.z = fmaxf(outacc[2], 0.f); v0.w = fmaxf(outacc[3], 0.f);
    v1.x = fmaxf(outacc[4], 0.f); v1.y = fmaxf(outacc[5], 0.f);
    v1.z = fmaxf(outacc[6], 0.f); v1.w = fmaxf(outacc[7], 0.f);
    *(float4*)o = v0; *(float4*)(o + 4) = v1;
}

__global__ void __launch_bounds__(256) k_gather_state(float* __restrict__ out) {
    int warp = threadIdx.x >> 5, lane = threadIdx.x & 31;
    int node = blockIdx.x * 8 + warp;
    if (node >= NS) return;
    int hq = lane >> 2;

    float outacc[8] = {};
    acc_half8(outacc, 1.f, g_Wh_in + (size_t)node * HD + lane * 8);  // self term

    #pragma unroll 1
    for (int t = 0; t < 3; t++) {
        int beg = g_off_cs[t * NS + node];
        int cnt = g_cnt_cs[t * NS + node];
        if (cnt == 0) continue;
        float invs = g_invs_cs[((size_t)t * NS + node) * H + hq];
        const __half* Wh = g_Wh_cs + (size_t)t * NC * HD;
        const int* csr = g_csr_cs + (size_t)t * ECS;
        const float* coef = g_coef_cs + (size_t)t * ECS * H;
        float acc[8] = {};
        #pragma unroll 4
        for (int e = 0; e < cnt; e++) {
            int src = __ldg(&csr[beg + e]);
            float cf = __ldg(&coef[(size_t)(beg + e) * H + hq]);
            acc_half8(acc, cf, Wh + (size_t)src * HD + lane * 8);
        }
        #pragma unroll
        for (int j = 0; j < 8; j++) outacc[j] += acc[j] * invs;
    }
    float* o = out + (size_t)3 * NC * HD + (size_t)node * HD + lane * 8;
    float4 v0, v1;
    v0.x = fmaxf(outacc[0], 0.f); v0.y = fmaxf(outacc[1], 0.f);
    v0.z = fmaxf(outacc[2], 0.f); v0.w = fmaxf(outacc[3], 0.f);
    v1.x = fmaxf(outacc[4], 0.f); v1.y = fmaxf(outacc[5], 0.f);
    v1.z = fmaxf(outacc[6], 0.f); v1.w = fmaxf(outacc[7], 0.f);
    *(float4*)o = v0; *(float4*)(o + 4) = v1;
}

// ---------------- launch ----------------
extern "C" void kernel_launch(void* const* d_in, const int* in_sizes, int n_in,
                              void* d_out, int out_size) {
    const float* f1      = (const float*)d_in[0];
    const float* f2      = (const float*)d_in[1];
    const float* f3      = (const float*)d_in[2];
    const float* fs      = (const float*)d_in[3];
    const float* W_node  = (const float*)d_in[4];
    const float* b_node  = (const float*)d_in[5];
    const float* W_cc    = (const float*)d_in[6];
    const float* b_cc    = (const float*)d_in[7];
    const float* W_cs    = (const float*)d_in[8];
    const float* b_cs    = (const float*)d_in[9];
    const float* W_in    = (const float*)d_in[10];
    const float* b_in    = (const float*)d_in[11];
    const float* attn_cc = (const float*)d_in[12];
    const float* attn_cs = (const float*)d_in[13];
    const int* ecc_src   = (const int*)d_in[14];
    const int* ecc_dst   = (const int*)d_in[15];
    const int* ecs_src   = (const int*)d_in[16];
    const int* ecs_dst   = (const int*)d_in[17];
    float* out = (float*)d_out;

    k_zero_counters<<<(9 * NC + 255) / 256, 256>>>();
    k_wred<<<(24 * INC * H + 255) / 256, 256>>>(W_node, b_node, W_cc, b_cc, W_cs, b_cs, W_in, b_in, attn_cc, attn_cs);
    k_skinny<<<dim3(1250, 4), 256>>>(f1, f2, f3, fs);
    int tot = 9 * ECC + 3 * ECS;
    k_hist<<<(tot + 255) / 256, 256>>>(ecc_dst, ecs_dst);
    k_scan<<<12, 1024>>>();
    k_scatter<<<(tot + 255) / 256, 256>>>(ecc_src, ecc_dst, ecs_src, ecs_dst);
    k_coef<<<dim3(1250, 12), 256>>>();
    k_gemm<<<dim3(79, 2, 13), 256>>>(f1, f2, f3, fs, W_cc, b_cc, W_cs, b_cs, W_in, b_in);
    k_gather_cc<<<dim3(1250, 3), 256>>>(out);
    k_gather_state<<<128, 256>>>(out);
}

// round 6
// speedup vs baseline: 1.7251x; 1.0978x over previous
#include <cuda_runtime.h>
#include <cuda_fp16.h>
#include <cstdint>

#define H   8
#define Dd  32
#define HD  256
#define NC  10000
#define NS  1024
#define INC 128
#define INS 64
#define ECC 120000
#define ECS 10000
#define LALPHA 0.2f
#define NEG_BIG -1e30f

// ---------------- device scratch (static; no runtime allocation) ----------------
__device__ __half g_Wh_cc[9u * NC * HD];     // 46 MB (fp16)
__device__ __half g_Wh_cs[3u * NC * HD];     // 15 MB
__device__ __half g_Wh_in[NS * HD];

__device__ float g_as_cc[9 * NC * H];
__device__ float g_ad_cc[9 * NC * H];
__device__ float g_as_cs[3 * NC * H];
__device__ float g_ad_s[3 * NS * H];

__device__ float g_wred_as[9 * INC * H];
__device__ float g_wred_ad[9 * INC * H];
__device__ float g_wred_as_cs[3 * INC * H];
__device__ float g_wred_ad_s[3 * INS * H];
__device__ float g_bred_as[9 * H];
__device__ float g_bred_ad[9 * H];
__device__ float g_bred_as_cs[3 * H];
__device__ float g_bred_ad_s[3 * H];

__device__ int g_cnt_cc[9 * NC];
__device__ int g_off_cc[9 * NC];
__device__ int g_cur_cc[9 * NC];
__device__ int g_csr_cc[9 * ECC];
__device__ int g_cnt_cs[3 * NS];
__device__ int g_off_cs[3 * NS];
__device__ int g_cur_cs[3 * NS];
__device__ int g_csr_cs[3 * ECS];

// ---------------- zero counters ----------------
__global__ void k_zero_counters() {
    int i = blockIdx.x * blockDim.x + threadIdx.x;
    if (i < 9 * NC) g_cnt_cc[i] = 0;
    if (i < 3 * NS) g_cnt_cs[i] = 0;
}

// ---------------- reduce attention vectors into weights ----------------
__global__ void k_wred(const float* __restrict__ W_node, const float* __restrict__ b_node,
                       const float* __restrict__ W_cc,   const float* __restrict__ b_cc,
                       const float* __restrict__ W_cs,   const float* __restrict__ b_cs,
                       const float* __restrict__ W_in,   const float* __restrict__ b_in,
                       const float* __restrict__ attn_cc, const float* __restrict__ attn_cs) {
    int gid = blockIdx.x * blockDim.x + threadIdx.x;
    if (gid >= 24 * INC * H) return;
    int j   = gid / (INC * H);
    int rem = gid % (INC * H);
    int k = rem / H, h = rem % H;
    const float *Wsrc, *att, *bvec;
    float *dst, *bdst;
    int Kin = INC;
    if (j < 9) {
        Wsrc = W_cc + (size_t)j * INC * HD;
        att  = attn_cc + (size_t)(j * 2 + 0) * HD;
        bvec = b_cc + (size_t)j * HD;
        dst  = g_wred_as + j * INC * H; bdst = g_bred_as + j * H;
    } else if (j < 18) {
        int r = j - 9;
        Wsrc = W_node + (size_t)(r % 3) * INC * HD;
        att  = attn_cc + (size_t)(r * 2 + 1) * HD;
        bvec = b_node + (size_t)(r % 3) * HD;
        dst  = g_wred_ad + r * INC * H; bdst = g_bred_ad + r * H;
    } else if (j < 21) {
        int t = j - 18;
        Wsrc = W_cs + (size_t)t * INC * HD;
        att  = attn_cs + (size_t)(t * 2 + 0) * HD;
        bvec = b_cs + (size_t)t * HD;
        dst  = g_wred_as_cs + t * INC * H; bdst = g_bred_as_cs + t * H;
    } else {
        int t = j - 21;
        Wsrc = W_in;
        att  = attn_cs + (size_t)(t * 2 + 1) * HD;
        bvec = b_in;
        dst  = g_wred_ad_s + t * INS * H; bdst = g_bred_ad_s + t * H;
        Kin = INS;
    }
    if (k >= Kin) return;
    float s = 0.f;
    #pragma unroll
    for (int d = 0; d < Dd; d++)
        s += Wsrc[(size_t)k * HD + h * Dd + d] * att[h * Dd + d];
    dst[k * H + h] = s;
    if (k == 0) {
        float bs = 0.f;
        #pragma unroll
        for (int d = 0; d < Dd; d++) bs += bvec[h * Dd + d] * att[h * Dd + d];
        bdst[h] = bs;
    }
}

// ---------------- fused skinny GEMMs: one pass over each node type ----------
__global__ void __launch_bounds__(256) k_skinny(const float* __restrict__ f1,
                                                const float* __restrict__ f2,
                                                const float* __restrict__ f3,
                                                const float* __restrict__ fs) {
    int t = blockIdx.y;
    __shared__ float Ws[7][H][INC];
    __shared__ float bsm[7][H];
    __shared__ const float* wptr[7];
    __shared__ float* optr[7];
    __shared__ const float* bptr[7];

    int Kin = (t < 3) ? INC : INS;
    int nG  = (t < 3) ? 7 : 3;
    int nNodes = (t < 3) ? NC : NS;
    const float* feat = (t == 0) ? f1 : (t == 1) ? f2 : (t == 2) ? f3 : fs;

    if (threadIdx.x < (unsigned)nG) {
        int g = threadIdx.x;
        if (t < 3) {
            if (g < 3) {
                int r = t * 3 + g;
                wptr[g] = g_wred_as + r * INC * H;
                bptr[g] = g_bred_as + r * H;
                optr[g] = g_as_cc + (size_t)r * NC * H;
            } else if (g < 6) {
                int r = (g - 3) * 3 + t;
                wptr[g] = g_wred_ad + r * INC * H;
                bptr[g] = g_bred_ad + r * H;
                optr[g] = g_ad_cc + (size_t)r * NC * H;
            } else {
                wptr[g] = g_wred_as_cs + t * INC * H;
                bptr[g] = g_bred_as_cs + t * H;
                optr[g] = g_as_cs + (size_t)t * NC * H;
            }
        } else {
            wptr[g] = g_wred_ad_s + g * INS * H;
            bptr[g] = g_bred_ad_s + g * H;
            optr[g] = g_ad_s + (size_t)g * NS * H;
        }
    }
    __syncthreads();

    for (int idx = threadIdx.x; idx < nG * H * Kin; idx += 256) {
        int g = idx / (H * Kin);
        int rem = idx % (H * Kin);
        int h = rem / Kin, k = rem % Kin;
        Ws[g][h][k] = wptr[g][k * H + h];
    }
    if (threadIdx.x < (unsigned)(nG * H)) {
        int g = threadIdx.x / H, h = threadIdx.x % H;
        bsm[g][h] = bptr[g][h];
    }
    __syncthreads();

    int warp = threadIdx.x >> 5, lane = threadIdx.x & 31;
    int node = blockIdx.x * 8 + warp;
    if (node >= nNodes) return;
    const float* frow = feat + (size_t)node * Kin;
    float f[4];
    int nc = Kin / 32;
    for (int c = 0; c < nc; c++) f[c] = frow[c * 32 + lane];

    for (int g = 0; g < nG; g++) {
        float mine = 0.f;
        #pragma unroll
        for (int h = 0; h < H; h++) {
            float v = 0.f;
            for (int c = 0; c < nc; c++) v += f[c] * Ws[g][h][c * 32 + lane];
            #pragma unroll
            for (int o = 16; o > 0; o >>= 1) v += __shfl_xor_sync(0xffffffffu, v, o);
            if (lane == h) mine = v;
        }
        if (lane < H) optr[g][(size_t)node * H + lane] = mine + bsm[g][lane];
    }
}

// ---------------- TF32 tensor-core GEMM helpers ----------------
__device__ __forceinline__ unsigned f2tf32(float x) {
    unsigned u; asm("cvt.rna.tf32.f32 %0, %1;" : "=r"(u) : "f"(x)); return u;
}
__device__ __forceinline__ void mma_tf32(float c[4], const unsigned a[4], const unsigned b[2]) {
    asm volatile("mma.sync.aligned.m16n8k8.row.col.f32.tf32.tf32.f32 "
        "{%0,%1,%2,%3}, {%4,%5,%6,%7}, {%8,%9}, {%0,%1,%2,%3};"
        : "+f"(c[0]), "+f"(c[1]), "+f"(c[2]), "+f"(c[3])
        : "r"(a[0]), "r"(a[1]), "r"(a[2]), "r"(a[3]), "r"(b[0]), "r"(b[1]));
}

// ---------------- big GEMMs: 13 jobs, TF32 MMA, fp16 output ----------------
__global__ void __launch_bounds__(256, 2) k_gemm(const float* __restrict__ f1, const float* __restrict__ f2,
                                                 const float* __restrict__ f3, const float* __restrict__ fs,
                                                 const float* __restrict__ Wcc, const float* __restrict__ bcc,
                                                 const float* __restrict__ Wcs, const float* __restrict__ bcs,
                                                 const float* __restrict__ Win, const float* __restrict__ bin) {
    int z = blockIdx.z;
    const float* A; const float* W; const float* bptr; __half* outp; int M, K;
    if (z < 9) {
        int s = z / 3;
        A = (s == 0) ? f1 : (s == 1) ? f2 : f3;
        W = Wcc + (size_t)z * INC * HD; bptr = bcc + (size_t)z * HD;
        outp = g_Wh_cc + (size_t)z * NC * HD; M = NC; K = INC;
    } else if (z < 12) {
        int t = z - 9;
        A = (t == 0) ? f1 : (t == 1) ? f2 : f3;
        W = Wcs + (size_t)t * INC * HD; bptr = bcs + (size_t)t * HD;
        outp = g_Wh_cs + (size_t)t * NC * HD; M = NC; K = INC;
    } else {
        A = fs; W = Win; bptr = bin; outp = g_Wh_in; M = NS; K = INS;
    }
    int row0 = blockIdx.x * 128;
    if (row0 >= M) return;
    int col0 = blockIdx.y * 128;

    __shared__ unsigned As[2][128][20];
    __shared__ unsigned Bs[2][16][132];

    int tid = threadIdx.x;
    int warp = tid >> 5, lane = tid & 31;
    int wm = warp & 3, wn = warp >> 2;
    int gr = lane >> 2, lc = lane & 3;

    int ar = tid >> 2, ak = (tid & 3) * 4;
    int br = tid >> 5, bc = (tid & 31) * 4;

    float4 la[2], lb[2];
    float c[2][8][4];
    #pragma unroll
    for (int mi = 0; mi < 2; mi++)
        #pragma unroll
        for (int ni = 0; ni < 8; ni++)
            #pragma unroll
            for (int q = 0; q < 4; q++) c[mi][ni][q] = 0.f;

    #pragma unroll
    for (int i = 0; i < 2; i++) {
        int r = ar + i * 64;
        la[i] = make_float4(0.f, 0.f, 0.f, 0.f);
        if (row0 + r < M) la[i] = *(const float4*)(A + (size_t)(row0 + r) * K + ak);
        lb[i] = *(const float4*)(W + (size_t)(br + i * 8) * HD + col0 + bc);
    }
    #pragma unroll
    for (int i = 0; i < 2; i++) {
        int r = ar + i * 64;
        As[0][r][ak + 0] = f2tf32(la[i].x); As[0][r][ak + 1] = f2tf32(la[i].y);
        As[0][r][ak + 2] = f2tf32(la[i].z); As[0][r][ak + 3] = f2tf32(la[i].w);
        unsigned* bp = &Bs[0][br + i * 8][bc];
        bp[0] = f2tf32(lb[i].x); bp[1] = f2tf32(lb[i].y);
        bp[2] = f2tf32(lb[i].z); bp[3] = f2tf32(lb[i].w);
    }
    __syncthreads();

    int nk = K / 16;
    for (int kc = 0; kc < nk; kc++) {
        int buf = kc & 1;
        bool nxt = (kc + 1) < nk;
        if (nxt) {
            int kt = (kc + 1) * 16;
            #pragma unroll
            for (int i = 0; i < 2; i++) {
                int r = ar + i * 64;
                la[i] = make_float4(0.f, 0.f, 0.f, 0.f);
                if (row0 + r < M) la[i] = *(const float4*)(A + (size_t)(row0 + r) * K + kt + ak);
                lb[i] = *(const float4*)(W + (size_t)(kt + br + i * 8) * HD + col0 + bc);
            }
        }
        #pragma unroll
        for (int ks = 0; ks < 2; ks++) {
            int k = ks * 8;
            unsigned a[2][4], b[8][2];
            #pragma unroll
            for (int mi = 0; mi < 2; mi++) {
                int rb = wm * 32 + mi * 16 + gr;
                a[mi][0] = As[buf][rb][k + lc];
                a[mi][1] = As[buf][rb + 8][k + lc];
                a[mi][2] = As[buf][rb][k + lc + 4];
                a[mi][3] = As[buf][rb + 8][k + lc + 4];
            }
            #pragma unroll
            for (int ni = 0; ni < 8; ni++) {
                int cb = wn * 64 + ni * 8 + gr;
                b[ni][0] = Bs[buf][k + lc][cb];
                b[ni][1] = Bs[buf][k + lc + 4][cb];
            }
            #pragma unroll
            for (int mi = 0; mi < 2; mi++)
                #pragma unroll
                for (int ni = 0; ni < 8; ni++)
                    mma_tf32(c[mi][ni], a[mi], b[ni]);
        }
        if (nxt) {
            int nb = buf ^ 1;
            #pragma unroll
            for (int i = 0; i < 2; i++) {
                int r = ar + i * 64;
                As[nb][r][ak + 0] = f2tf32(la[i].x); As[nb][r][ak + 1] = f2tf32(la[i].y);
                As[nb][r][ak + 2] = f2tf32(la[i].z); As[nb][r][ak + 3] = f2tf32(la[i].w);
                unsigned* bp = &Bs[nb][br + i * 8][bc];
                bp[0] = f2tf32(lb[i].x); bp[1] = f2tf32(lb[i].y);
                bp[2] = f2tf32(lb[i].z); bp[3] = f2tf32(lb[i].w);
            }
        }
        __syncthreads();
    }

    #pragma unroll
    for (int mi = 0; mi < 2; mi++) {
        int r0 = row0 + wm * 32 + mi * 16 + gr;
        #pragma unroll
        for (int ni = 0; ni < 8; ni++) {
            int cl = col0 + wn * 64 + ni * 8 + lc * 2;
            float b0 = bptr[cl], b1 = bptr[cl + 1];
            if (r0 < M)
                *(__half2*)(outp + (size_t)r0 * HD + cl) =
                    __floats2half2_rn(c[mi][ni][0] + b0, c[mi][ni][1] + b1);
            if (r0 + 8 < M)
                *(__half2*)(outp + (size_t)(r0 + 8) * HD + cl) =
                    __floats2half2_rn(c[mi][ni][2] + b0, c[mi][ni][3] + b1);
        }
    }
}

// ---------------- CSR build: histogram, scan, scatter ----------------
__global__ void k_hist(const int* __restrict__ ecc_dst, const int* __restrict__ ecs_dst) {
    int gid = blockIdx.x * blockDim.x + threadIdx.x;
    if (gid < 9 * ECC) {
        int r = gid / ECC;
        atomicAdd(&g_cnt_cc[r * NC + ecc_dst[gid]], 1);
    } else if (gid < 9 * ECC + 3 * ECS) {
        int g = gid - 9 * ECC;
        int t = g / ECS;
        atomicAdd(&g_cnt_cs[t * NS + ecs_dst[g]], 1);
    }
}

__global__ void __launch_bounds__(1024) k_scan() {
    int rel = blockIdx.x;
    int n; int* cnt; int* off; int* cur;
    if (rel < 9) { n = NC; cnt = g_cnt_cc + rel * NC; off = g_off_cc + rel * NC; cur = g_cur_cc + rel * NC; }
    else { int t = rel - 9; n = NS; cnt = g_cnt_cs + t * NS; off = g_off_cs + t * NS; cur = g_cur_cs + t * NS; }
    int tid = threadIdx.x;
    int CH = (n + 1023) / 1024;
    int base = tid * CH;
    int loc[10]; int s = 0;
    for (int i = 0; i < CH; i++) {
        int v = (base + i < n) ? cnt[base + i] : 0;
        loc[i] = s; s += v;
    }
    __shared__ int sums[1024];
    sums[tid] = s; __syncthreads();
    for (int o = 1; o < 1024; o <<= 1) {
        int v = (tid >= o) ? sums[tid - o] : 0;
        __syncthreads();
        sums[tid] += v;
        __syncthreads();
    }
    int prefix = (tid == 0) ? 0 : sums[tid - 1];
    for (int i = 0; i < CH; i++) if (base + i < n) {
        int o2 = prefix + loc[i];
        off[base + i] = o2;
        cur[base + i] = o2;
    }
}

__global__ void k_scatter(const int* __restrict__ ecc_src, const int* __restrict__ ecc_dst,
                          const int* __restrict__ ecs_src, const int* __restrict__ ecs_dst) {
    int gid = blockIdx.x * blockDim.x + threadIdx.x;
    if (gid < 9 * ECC) {
        int r = gid / ECC;
        int pos = atomicAdd(&g_cur_cc[r * NC + ecc_dst[gid]], 1);
        g_csr_cc[r * ECC + pos] = ecc_src[gid];
    } else if (gid < 9 * ECC + 3 * ECS) {
        int g = gid - 9 * ECC;
        int t = g / ECS;
        int pos = atomicAdd(&g_cur_cs[t * NS + ecs_dst[g]], 1);
        g_csr_cs[t * ECS + pos] = ecs_src[g];
    }
}

// ---------------- fused softmax + gather ----------------
__device__ __forceinline__ float lrelu(float x) { return x > 0.f ? x : LALPHA * x; }

__device__ __forceinline__ void acc_half8(float acc[8], float cf, const __half* wr) {
    uint4 u = *(const uint4*)wr;
    __half2 h0 = *(__half2*)&u.x, h1 = *(__half2*)&u.y;
    __half2 h2 = *(__half2*)&u.z, h3 = *(__half2*)&u.w;
    float2 f0 = __half22float2(h0), f1 = __half22float2(h1);
    float2 f2 = __half22float2(h2), f3 = __half22float2(h3);
    acc[0] += cf * f0.x; acc[1] += cf * f0.y;
    acc[2] += cf * f1.x; acc[3] += cf * f1.y;
    acc[4] += cf * f2.x; acc[5] += cf * f2.y;
    acc[6] += cf * f3.x; acc[7] += cf * f3.y;
}

// One warp handles one (node, relation): pass 1 = logits + scalar max,
// pass 2 (per 32-edge chunk) = exp -> smem, then sequential coalesced gather.
// lsum[hq] extraction via 3-level select tree (hq = lane>>2).
__device__ __forceinline__ float sel8(const float v[8], int hq) {
    float a = (hq & 1) ? v[1] : v[0];
    float b = (hq & 1) ? v[3] : v[2];
    float c = (hq & 1) ? v[5] : v[4];
    float d = (hq & 1) ? v[7] : v[6];
    float ab = (hq & 2) ? b : a;
    float cd = (hq & 2) ? d : c;
    return (hq & 4) ? cd : ab;
}

__device__ __forceinline__ void gat_relation(
    int node, int lane, int warp, int hq, int beg, int cnt,
    const float* __restrict__ asb, const float* __restrict__ adp,
    const int* __restrict__ csr, const __half* __restrict__ Wh,
    float pbuf[8][32][H], int sbuf[8][32], float outacc[8])
{
    float ad[H];
    {
        float4 a0 = *(const float4*)adp;
        float4 a1 = *(const float4*)(adp + 4);
        ad[0]=a0.x; ad[1]=a0.y; ad[2]=a0.z; ad[3]=a0.w;
        ad[4]=a1.x; ad[5]=a1.y; ad[6]=a1.z; ad[7]=a1.w;
    }
    // pass 1: logits for all edges; scalar warp max (stability only)
    float mymax = NEG_BIG;
    float ev0[H]; int src0 = 0;
    for (int e = lane; e < cnt; e += 32) {
        int src = __ldg(&csr[beg + e]);
        float4 s0 = *(const float4*)(asb + (size_t)src * H);
        float4 s1 = *(const float4*)(asb + (size_t)src * H + 4);
        float ev[H];
        ev[0]=lrelu(s0.x+ad[0]); ev[1]=lrelu(s0.y+ad[1]); ev[2]=lrelu(s0.z+ad[2]); ev[3]=lrelu(s0.w+ad[3]);
        ev[4]=lrelu(s1.x+ad[4]); ev[5]=lrelu(s1.y+ad[5]); ev[6]=lrelu(s1.z+ad[6]); ev[7]=lrelu(s1.w+ad[7]);
        if (e == lane) {
            #pragma unroll
            for (int h = 0; h < H; h++) ev0[h] = ev[h];
            src0 = src;
        }
        #pragma unroll
        for (int h = 0; h < H; h++) mymax = fmaxf(mymax, ev[h]);
    }
    #pragma unroll
    for (int o = 16; o > 0; o >>= 1)
        mymax = fmaxf(mymax, __shfl_xor_sync(0xffffffffu, mymax, o));

    float lsum[H];
    #pragma unroll
    for (int h = 0; h < H; h++) lsum[h] = 0.f;
    float acc[8] = {};
    int nchunk = (cnt + 31) >> 5;
    for (int c = 0; c < nchunk; c++) {
        int e = c * 32 + lane;
        float p[H];
        int src = 0;
        if (e < cnt) {
            float ev[H];
            if (c == 0) {
                #pragma unroll
                for (int h = 0; h < H; h++) ev[h] = ev0[h];
                src = src0;
            } else {
                src = __ldg(&csr[beg + e]);
                float4 s0 = *(const float4*)(asb + (size_t)src * H);
                float4 s1 = *(const float4*)(asb + (size_t)src * H + 4);
                ev[0]=lrelu(s0.x+ad[0]); ev[1]=lrelu(s0.y+ad[1]); ev[2]=lrelu(s0.z+ad[2]); ev[3]=lrelu(s0.w+ad[3]);
                ev[4]=lrelu(s1.x+ad[4]); ev[5]=lrelu(s1.y+ad[5]); ev[6]=lrelu(s1.z+ad[6]); ev[7]=lrelu(s1.w+ad[7]);
            }
            #pragma unroll
            for (int h = 0; h < H; h++) { p[h] = __expf(ev[h] - mymax); lsum[h] += p[h]; }
        } else {
            #pragma unroll
            for (int h = 0; h < H; h++) p[h] = 0.f;
        }
        sbuf[warp][lane] = src;
        #pragma unroll
        for (int h = 0; h < H; h++) pbuf[warp][lane][h] = p[h];
        __syncwarp();
        int nv = min(32, cnt - c * 32);
        #pragma unroll 4
        for (int ee = 0; ee < nv; ee++) {
            int s2 = sbuf[warp][ee];
            float cf = pbuf[warp][ee][hq];
            acc_half8(acc, cf, Wh + (size_t)s2 * HD + lane * 8);
        }
        __syncwarp();
    }
    #pragma unroll
    for (int h = 0; h < H; h++)
        #pragma unroll
        for (int o = 16; o > 0; o >>= 1) lsum[h] += __shfl_xor_sync(0xffffffffu, lsum[h], o);
    float invs = 1.f / sel8(lsum, hq);
    #pragma unroll
    for (int j = 0; j < 8; j++) outacc[j] += acc[j] * invs;
}

__global__ void __launch_bounds__(256) k_gather_cc(float* __restrict__ out) {
    __shared__ float pbuf[8][32][H];
    __shared__ int   sbuf[8][32];
    int dt = blockIdx.y;
    int warp = threadIdx.x >> 5, lane = threadIdx.x & 31;
    int node = blockIdx.x * 8 + warp;
    if (node >= NC) return;
    int hq = lane >> 2;

    float outacc[8] = {};
    #pragma unroll 1
    for (int s = 0; s < 3; s++) {
        int r = 3 * s + dt;
        int beg = g_off_cc[r * NC + node];
        int cnt = g_cnt_cc[r * NC + node];
        if (cnt == 0) continue;
        gat_relation(node, lane, warp, hq, beg, cnt,
                     g_as_cc + (size_t)r * NC * H,
                     g_ad_cc + ((size_t)r * NC + node) * H,
                     g_csr_cc + (size_t)r * ECC,
                     g_Wh_cc + (size_t)r * NC * HD,
                     pbuf, sbuf, outacc);
    }
    float* o = out + ((size_t)dt * NC + node) * HD + lane * 8;
    float4 v0, v1;
    v0.x = fmaxf(outacc[0], 0.f); v0.y = fmaxf(outacc[1], 0.f);
    v0.z = fmaxf(outacc[2], 0.f); v0.w = fmaxf(outacc[3], 0.f);
    v1.x = fmaxf(outacc[4], 0.f); v1.y = fmaxf(outacc[5], 0.f);
    v1.z = fmaxf(outacc[6], 0.f); v1.w = fmaxf(outacc[7], 0.f);
    *(float4*)o = v0; *(float4*)(o + 4) = v1;
}

__global__ void __launch_bounds__(256) k_gather_state(float* __restrict__ out) {
    __shared__ float pbuf[8][32][H];
    __shared__ int   sbuf[8][32];
    int warp = threadIdx.x >> 5, lane = threadIdx.x & 31;
    int node = blockIdx.x * 8 + warp;
    if (node >= NS) return;
    int hq = lane >> 2;

    float outacc[8] = {};
    acc_half8(outacc, 1.f, g_Wh_in + (size_t)node * HD + lane * 8);  // self term

    #pragma unroll 1
    for (int t = 0; t < 3; t++) {
        int beg = g_off_cs[t * NS + node];
        int cnt = g_cnt_cs[t * NS + node];
        if (cnt == 0) continue;
        gat_relation(node, lane, warp, hq, beg, cnt,
                     g_as_cs + (size_t)t * NC * H,
                     g_ad_s + ((size_t)t * NS + node) * H,
                     g_csr_cs + (size_t)t * ECS,
                     g_Wh_cs + (size_t)t * NC * HD,
                     pbuf, sbuf, outacc);
    }
    float* o = out + (size_t)3 * NC * HD + (size_t)node * HD + lane * 8;
    float4 v0, v1;
    v0.x = fmaxf(outacc[0], 0.f); v0.y = fmaxf(outacc[1], 0.f);
    v0.z = fmaxf(outacc[2], 0.f); v0.w = fmaxf(outacc[3], 0.f);
    v1.x = fmaxf(outacc[4], 0.f); v1.y = fmaxf(outacc[5], 0.f);
    v1.z = fmaxf(outacc[6], 0.f); v1.w = fmaxf(outacc[7], 0.f);
    *(float4*)o = v0; *(float4*)(o + 4) = v1;
}

// ---------------- launch ----------------
extern "C" void kernel_launch(void* const* d_in, const int* in_sizes, int n_in,
                              void* d_out, int out_size) {
    const float* f1      = (const float*)d_in[0];
    const float* f2      = (const float*)d_in[1];
    const float* f3      = (const float*)d_in[2];
    const float* fs      = (const float*)d_in[3];
    const float* W_node  = (const float*)d_in[4];
    const float* b_node  = (const float*)d_in[5];
    const float* W_cc    = (const float*)d_in[6];
    const float* b_cc    = (const float*)d_in[7];
    const float* W_cs    = (const float*)d_in[8];
    const float* b_cs    = (const float*)d_in[9];
    const float* W_in    = (const float*)d_in[10];
    const float* b_in    = (const float*)d_in[11];
    const float* attn_cc = (const float*)d_in[12];
    const float* attn_cs = (const float*)d_in[13];
    const int* ecc_src   = (const int*)d_in[14];
    const int* ecc_dst   = (const int*)d_in[15];
    const int* ecs_src   = (const int*)d_in[16];
    const int* ecs_dst   = (const int*)d_in[17];
    float* out = (float*)d_out;

    k_zero_counters<<<(9 * NC + 255) / 256, 256>>>();
    k_wred<<<(24 * INC * H + 255) / 256, 256>>>(W_node, b_node, W_cc, b_cc, W_cs, b_cs, W_in, b_in, attn_cc, attn_cs);
    k_skinny<<<dim3(1250, 4), 256>>>(f1, f2, f3, fs);
    int tot = 9 * ECC + 3 * ECS;
    k_hist<<<(tot + 255) / 256, 256>>>(ecc_dst, ecs_dst);
    k_scan<<<12, 1024>>>();
    k_scatter<<<(tot + 255) / 256, 256>>>(ecc_src, ecc_dst, ecs_src, ecs_dst);
    k_gemm<<<dim3(79, 2, 13), 256>>>(f1, f2, f3, fs, W_cc, b_cc, W_cs, b_cs, W_in, b_in);
    k_gather_cc<<<dim3(1250, 3), 256>>>(out);
    k_gather_state<<<128, 256>>>(out);
}

// round 7
// speedup vs baseline: 1.7869x; 1.0359x over previous
#include <cuda_runtime.h>
#include <cuda_fp16.h>
#include <cstdint>

#define H   8
#define Dd  32
#define HD  256
#define NC  10000
#define NS  1024
#define INC 128
#define INS 64
#define ECC 120000
#define ECS 10000
#define LALPHA 0.2f
#define NEG_BIG -1e30f

// ---------------- device scratch (static; no runtime allocation) ----------------
__device__ __half g_Wh_cc[9u * NC * HD];     // 46 MB (fp16)
__device__ __half g_Wh_cs[3u * NC * HD];     // 15 MB
__device__ __half g_Wh_in[NS * HD];

__device__ float g_as_cc[9 * NC * H];
__device__ float g_ad_cc[9 * NC * H];
__device__ float g_as_cs[3 * NC * H];
__device__ float g_ad_s[3 * NS * H];

__device__ float g_asmax[12 * H];            // per-(relation, head) max of a_src

__device__ float g_wred_as[9 * INC * H];
__device__ float g_wred_ad[9 * INC * H];
__device__ float g_wred_as_cs[3 * INC * H];
__device__ float g_wred_ad_s[3 * INS * H];
__device__ float g_bred_as[9 * H];
__device__ float g_bred_ad[9 * H];
__device__ float g_bred_as_cs[3 * H];
__device__ float g_bred_ad_s[3 * H];

__device__ int g_cnt_cc[9 * NC];
__device__ int g_off_cc[9 * NC];
__device__ int g_cur_cc[9 * NC];
__device__ int g_csr_cc[9 * ECC];
__device__ int g_cnt_cs[3 * NS];
__device__ int g_off_cs[3 * NS];
__device__ int g_cur_cs[3 * NS];
__device__ int g_csr_cs[3 * ECS];

// ---------------- zero counters ----------------
__global__ void k_zero_counters() {
    int i = blockIdx.x * blockDim.x + threadIdx.x;
    if (i < 9 * NC) g_cnt_cc[i] = 0;
    if (i < 3 * NS) g_cnt_cs[i] = 0;
}

// ---------------- reduce attention vectors into weights ----------------
__global__ void k_wred(const float* __restrict__ W_node, const float* __restrict__ b_node,
                       const float* __restrict__ W_cc,   const float* __restrict__ b_cc,
                       const float* __restrict__ W_cs,   const float* __restrict__ b_cs,
                       const float* __restrict__ W_in,   const float* __restrict__ b_in,
                       const float* __restrict__ attn_cc, const float* __restrict__ attn_cs) {
    int gid = blockIdx.x * blockDim.x + threadIdx.x;
    if (gid >= 24 * INC * H) return;
    int j   = gid / (INC * H);
    int rem = gid % (INC * H);
    int k = rem / H, h = rem % H;
    const float *Wsrc, *att, *bvec;
    float *dst, *bdst;
    int Kin = INC;
    if (j < 9) {
        Wsrc = W_cc + (size_t)j * INC * HD;
        att  = attn_cc + (size_t)(j * 2 + 0) * HD;
        bvec = b_cc + (size_t)j * HD;
        dst  = g_wred_as + j * INC * H; bdst = g_bred_as + j * H;
    } else if (j < 18) {
        int r = j - 9;
        Wsrc = W_node + (size_t)(r % 3) * INC * HD;
        att  = attn_cc + (size_t)(r * 2 + 1) * HD;
        bvec = b_node + (size_t)(r % 3) * HD;
        dst  = g_wred_ad + r * INC * H; bdst = g_bred_ad + r * H;
    } else if (j < 21) {
        int t = j - 18;
        Wsrc = W_cs + (size_t)t * INC * HD;
        att  = attn_cs + (size_t)(t * 2 + 0) * HD;
        bvec = b_cs + (size_t)t * HD;
        dst  = g_wred_as_cs + t * INC * H; bdst = g_bred_as_cs + t * H;
    } else {
        int t = j - 21;
        Wsrc = W_in;
        att  = attn_cs + (size_t)(t * 2 + 1) * HD;
        bvec = b_in;
        dst  = g_wred_ad_s + t * INS * H; bdst = g_bred_ad_s + t * H;
        Kin = INS;
    }
    if (k >= Kin) return;
    float s = 0.f;
    #pragma unroll
    for (int d = 0; d < Dd; d++)
        s += Wsrc[(size_t)k * HD + h * Dd + d] * att[h * Dd + d];
    dst[k * H + h] = s;
    if (k == 0) {
        float bs = 0.f;
        #pragma unroll
        for (int d = 0; d < Dd; d++) bs += bvec[h * Dd + d] * att[h * Dd + d];
        bdst[h] = bs;
    }
}

// ---------------- fused skinny GEMMs: one pass over each node type ----------
__global__ void __launch_bounds__(256) k_skinny(const float* __restrict__ f1,
                                                const float* __restrict__ f2,
                                                const float* __restrict__ f3,
                                                const float* __restrict__ fs) {
    int t = blockIdx.y;
    __shared__ float Ws[7][H][INC];
    __shared__ float bsm[7][H];
    __shared__ const float* wptr[7];
    __shared__ float* optr[7];
    __shared__ const float* bptr[7];

    int Kin = (t < 3) ? INC : INS;
    int nG  = (t < 3) ? 7 : 3;
    int nNodes = (t < 3) ? NC : NS;
    const float* feat = (t == 0) ? f1 : (t == 1) ? f2 : (t == 2) ? f3 : fs;

    if (threadIdx.x < (unsigned)nG) {
        int g = threadIdx.x;
        if (t < 3) {
            if (g < 3) {
                int r = t * 3 + g;
                wptr[g] = g_wred_as + r * INC * H;
                bptr[g] = g_bred_as + r * H;
                optr[g] = g_as_cc + (size_t)r * NC * H;
            } else if (g < 6) {
                int r = (g - 3) * 3 + t;
                wptr[g] = g_wred_ad + r * INC * H;
                bptr[g] = g_bred_ad + r * H;
                optr[g] = g_ad_cc + (size_t)r * NC * H;
            } else {
                wptr[g] = g_wred_as_cs + t * INC * H;
                bptr[g] = g_bred_as_cs + t * H;
                optr[g] = g_as_cs + (size_t)t * NC * H;
            }
        } else {
            wptr[g] = g_wred_ad_s + g * INS * H;
            bptr[g] = g_bred_ad_s + g * H;
            optr[g] = g_ad_s + (size_t)g * NS * H;
        }
    }
    __syncthreads();

    for (int idx = threadIdx.x; idx < nG * H * Kin; idx += 256) {
        int g = idx / (H * Kin);
        int rem = idx % (H * Kin);
        int h = rem / Kin, k = rem % Kin;
        Ws[g][h][k] = wptr[g][k * H + h];
    }
    if (threadIdx.x < (unsigned)(nG * H)) {
        int g = threadIdx.x / H, h = threadIdx.x % H;
        bsm[g][h] = bptr[g][h];
    }
    __syncthreads();

    int warp = threadIdx.x >> 5, lane = threadIdx.x & 31;
    int node = blockIdx.x * 8 + warp;
    if (node >= nNodes) return;
    const float* frow = feat + (size_t)node * Kin;
    float f[4];
    int nc = Kin / 32;
    for (int c = 0; c < nc; c++) f[c] = frow[c * 32 + lane];

    for (int g = 0; g < nG; g++) {
        float mine = 0.f;
        #pragma unroll
        for (int h = 0; h < H; h++) {
            float v = 0.f;
            for (int c = 0; c < nc; c++) v += f[c] * Ws[g][h][c * 32 + lane];
            #pragma unroll
            for (int o = 16; o > 0; o >>= 1) v += __shfl_xor_sync(0xffffffffu, v, o);
            if (lane == h) mine = v;
        }
        if (lane < H) optr[g][(size_t)node * H + lane] = mine + bsm[g][lane];
    }
}

// ---------------- per-relation a_src max (for single-pass softmax) ----------
__global__ void __launch_bounds__(256) k_asmax() {
    int rel = blockIdx.x;                 // 0..8 cc, 9..11 cs
    const float* asb = (rel < 9) ? (g_as_cc + (size_t)rel * NC * H)
                                 : (g_as_cs + (size_t)(rel - 9) * NC * H);
    float mx[H];
    #pragma unroll
    for (int h = 0; h < H; h++) mx[h] = NEG_BIG;
    for (int i = threadIdx.x; i < NC; i += 256) {
        float4 a0 = *(const float4*)(asb + (size_t)i * H);
        float4 a1 = *(const float4*)(asb + (size_t)i * H + 4);
        mx[0]=fmaxf(mx[0],a0.x); mx[1]=fmaxf(mx[1],a0.y); mx[2]=fmaxf(mx[2],a0.z); mx[3]=fmaxf(mx[3],a0.w);
        mx[4]=fmaxf(mx[4],a1.x); mx[5]=fmaxf(mx[5],a1.y); mx[6]=fmaxf(mx[6],a1.z); mx[7]=fmaxf(mx[7],a1.w);
    }
    #pragma unroll
    for (int h = 0; h < H; h++)
        #pragma unroll
        for (int o = 16; o > 0; o >>= 1) mx[h] = fmaxf(mx[h], __shfl_xor_sync(0xffffffffu, mx[h], o));
    __shared__ float sm[8][H];
    int warp = threadIdx.x >> 5, lane = threadIdx.x & 31;
    if (lane == 0)
        #pragma unroll
        for (int h = 0; h < H; h++) sm[warp][h] = mx[h];
    __syncthreads();
    if (threadIdx.x < H) {
        float v = sm[0][threadIdx.x];
        #pragma unroll
        for (int w = 1; w < 8; w++) v = fmaxf(v, sm[w][threadIdx.x]);
        g_asmax[rel * H + threadIdx.x] = v;
    }
}

// ---------------- TF32 tensor-core GEMM helpers ----------------
__device__ __forceinline__ unsigned f2tf32(float x) {
    unsigned u; asm("cvt.rna.tf32.f32 %0, %1;" : "=r"(u) : "f"(x)); return u;
}
__device__ __forceinline__ void mma_tf32(float c[4], const unsigned a[4], const unsigned b[2]) {
    asm volatile("mma.sync.aligned.m16n8k8.row.col.f32.tf32.tf32.f32 "
        "{%0,%1,%2,%3}, {%4,%5,%6,%7}, {%8,%9}, {%0,%1,%2,%3};"
        : "+f"(c[0]), "+f"(c[1]), "+f"(c[2]), "+f"(c[3])
        : "r"(a[0]), "r"(a[1]), "r"(a[2]), "r"(a[3]), "r"(b[0]), "r"(b[1]));
}

// ---------------- big GEMMs: 13 jobs, TF32 MMA, fp16 output ----------------
__global__ void __launch_bounds__(256, 2) k_gemm(const float* __restrict__ f1, const float* __restrict__ f2,
                                                 const float* __restrict__ f3, const float* __restrict__ fs,
                                                 const float* __restrict__ Wcc, const float* __restrict__ bcc,
                                                 const float* __restrict__ Wcs, const float* __restrict__ bcs,
                                                 const float* __restrict__ Win, const float* __restrict__ bin) {
    int z = blockIdx.z;
    const float* A; const float* W; const float* bptr; __half* outp; int M, K;
    if (z < 9) {
        int s = z / 3;
        A = (s == 0) ? f1 : (s == 1) ? f2 : f3;
        W = Wcc + (size_t)z * INC * HD; bptr = bcc + (size_t)z * HD;
        outp = g_Wh_cc + (size_t)z * NC * HD; M = NC; K = INC;
    } else if (z < 12) {
        int t = z - 9;
        A = (t == 0) ? f1 : (t == 1) ? f2 : f3;
        W = Wcs + (size_t)t * INC * HD; bptr = bcs + (size_t)t * HD;
        outp = g_Wh_cs + (size_t)t * NC * HD; M = NC; K = INC;
    } else {
        A = fs; W = Win; bptr = bin; outp = g_Wh_in; M = NS; K = INS;
    }
    int row0 = blockIdx.x * 128;
    if (row0 >= M) return;
    int col0 = blockIdx.y * 128;

    __shared__ unsigned As[2][128][20];
    __shared__ unsigned Bs[2][16][132];

    int tid = threadIdx.x;
    int warp = tid >> 5, lane = tid & 31;
    int wm = warp & 3, wn = warp >> 2;
    int gr = lane >> 2, lc = lane & 3;

    int ar = tid >> 2, ak = (tid & 3) * 4;
    int br = tid >> 5, bc = (tid & 31) * 4;

    float4 la[2], lb[2];
    float c[2][8][4];
    #pragma unroll
    for (int mi = 0; mi < 2; mi++)
        #pragma unroll
        for (int ni = 0; ni < 8; ni++)
            #pragma unroll
            for (int q = 0; q < 4; q++) c[mi][ni][q] = 0.f;

    #pragma unroll
    for (int i = 0; i < 2; i++) {
        int r = ar + i * 64;
        la[i] = make_float4(0.f, 0.f, 0.f, 0.f);
        if (row0 + r < M) la[i] = *(const float4*)(A + (size_t)(row0 + r) * K + ak);
        lb[i] = *(const float4*)(W + (size_t)(br + i * 8) * HD + col0 + bc);
    }
    #pragma unroll
    for (int i = 0; i < 2; i++) {
        int r = ar + i * 64;
        As[0][r][ak + 0] = f2tf32(la[i].x); As[0][r][ak + 1] = f2tf32(la[i].y);
        As[0][r][ak + 2] = f2tf32(la[i].z); As[0][r][ak + 3] = f2tf32(la[i].w);
        unsigned* bp = &Bs[0][br + i * 8][bc];
        bp[0] = f2tf32(lb[i].x); bp[1] = f2tf32(lb[i].y);
        bp[2] = f2tf32(lb[i].z); bp[3] = f2tf32(lb[i].w);
    }
    __syncthreads();

    int nk = K / 16;
    for (int kc = 0; kc < nk; kc++) {
        int buf = kc & 1;
        bool nxt = (kc + 1) < nk;
        if (nxt) {
            int kt = (kc + 1) * 16;
            #pragma unroll
            for (int i = 0; i < 2; i++) {
                int r = ar + i * 64;
                la[i] = make_float4(0.f, 0.f, 0.f, 0.f);
                if (row0 + r < M) la[i] = *(const float4*)(A + (size_t)(row0 + r) * K + kt + ak);
                lb[i] = *(const float4*)(W + (size_t)(kt + br + i * 8) * HD + col0 + bc);
            }
        }
        #pragma unroll
        for (int ks = 0; ks < 2; ks++) {
            int k = ks * 8;
            unsigned a[2][4], b[8][2];
            #pragma unroll
            for (int mi = 0; mi < 2; mi++) {
                int rb = wm * 32 + mi * 16 + gr;
                a[mi][0] = As[buf][rb][k + lc];
                a[mi][1] = As[buf][rb + 8][k + lc];
                a[mi][2] = As[buf][rb][k + lc + 4];
                a[mi][3] = As[buf][rb + 8][k + lc + 4];
            }
            #pragma unroll
            for (int ni = 0; ni < 8; ni++) {
                int cb = wn * 64 + ni * 8 + gr;
                b[ni][0] = Bs[buf][k + lc][cb];
                b[ni][1] = Bs[buf][k + lc + 4][cb];
            }
            #pragma unroll
            for (int mi = 0; mi < 2; mi++)
                #pragma unroll
                for (int ni = 0; ni < 8; ni++)
                    mma_tf32(c[mi][ni], a[mi], b[ni]);
        }
        if (nxt) {
            int nb = buf ^ 1;
            #pragma unroll
            for (int i = 0; i < 2; i++) {
                int r = ar + i * 64;
                As[nb][r][ak + 0] = f2tf32(la[i].x); As[nb][r][ak + 1] = f2tf32(la[i].y);
                As[nb][r][ak + 2] = f2tf32(la[i].z); As[nb][r][ak + 3] = f2tf32(la[i].w);
                unsigned* bp = &Bs[nb][br + i * 8][bc];
                bp[0] = f2tf32(lb[i].x); bp[1] = f2tf32(lb[i].y);
                bp[2] = f2tf32(lb[i].z); bp[3] = f2tf32(lb[i].w);
            }
        }
        __syncthreads();
    }

    #pragma unroll
    for (int mi = 0; mi < 2; mi++) {
        int r0 = row0 + wm * 32 + mi * 16 + gr;
        #pragma unroll
        for (int ni = 0; ni < 8; ni++) {
            int cl = col0 + wn * 64 + ni * 8 + lc * 2;
            float b0 = bptr[cl], b1 = bptr[cl + 1];
            if (r0 < M)
                *(__half2*)(outp + (size_t)r0 * HD + cl) =
                    __floats2half2_rn(c[mi][ni][0] + b0, c[mi][ni][1] + b1);
            if (r0 + 8 < M)
                *(__half2*)(outp + (size_t)(r0 + 8) * HD + cl) =
                    __floats2half2_rn(c[mi][ni][2] + b0, c[mi][ni][3] + b1);
        }
    }
}

// ---------------- CSR build: histogram, scan, scatter ----------------
__global__ void k_hist(const int* __restrict__ ecc_dst, const int* __restrict__ ecs_dst) {
    int gid = blockIdx.x * blockDim.x + threadIdx.x;
    if (gid < 9 * ECC) {
        int r = gid / ECC;
        atomicAdd(&g_cnt_cc[r * NC + ecc_dst[gid]], 1);
    } else if (gid < 9 * ECC + 3 * ECS) {
        int g = gid - 9 * ECC;
        int t = g / ECS;
        atomicAdd(&g_cnt_cs[t * NS + ecs_dst[g]], 1);
    }
}

__global__ void __launch_bounds__(1024) k_scan() {
    int rel = blockIdx.x;
    int n; int* cnt; int* off; int* cur;
    if (rel < 9) { n = NC; cnt = g_cnt_cc + rel * NC; off = g_off_cc + rel * NC; cur = g_cur_cc + rel * NC; }
    else { int t = rel - 9; n = NS; cnt = g_cnt_cs + t * NS; off = g_off_cs + t * NS; cur = g_cur_cs + t * NS; }
    int tid = threadIdx.x;
    int CH = (n + 1023) / 1024;
    int base = tid * CH;
    int loc[10]; int s = 0;
    for (int i = 0; i < CH; i++) {
        int v = (base + i < n) ? cnt[base + i] : 0;
        loc[i] = s; s += v;
    }
    __shared__ int sums[1024];
    sums[tid] = s; __syncthreads();
    for (int o = 1; o < 1024; o <<= 1) {
        int v = (tid >= o) ? sums[tid - o] : 0;
        __syncthreads();
        sums[tid] += v;
        __syncthreads();
    }
    int prefix = (tid == 0) ? 0 : sums[tid - 1];
    for (int i = 0; i < CH; i++) if (base + i < n) {
        int o2 = prefix + loc[i];
        off[base + i] = o2;
        cur[base + i] = o2;
    }
}

__global__ void k_scatter(const int* __restrict__ ecc_src, const int* __restrict__ ecc_dst,
                          const int* __restrict__ ecs_src, const int* __restrict__ ecs_dst) {
    int gid = blockIdx.x * blockDim.x + threadIdx.x;
    if (gid < 9 * ECC) {
        int r = gid / ECC;
        int pos = atomicAdd(&g_cur_cc[r * NC + ecc_dst[gid]], 1);
        g_csr_cc[r * ECC + pos] = ecc_src[gid];
    } else if (gid < 9 * ECC + 3 * ECS) {
        int g = gid - 9 * ECC;
        int t = g / ECS;
        int pos = atomicAdd(&g_cur_cs[t * NS + ecs_dst[g]], 1);
        g_csr_cs[t * ECS + pos] = ecs_src[g];
    }
}

// ---------------- fused single-pass softmax + gather ----------------
__device__ __forceinline__ float lrelu(float x) { return x > 0.f ? x : LALPHA * x; }

__device__ __forceinline__ void acc_half8(float acc[8], float cf, const __half* wr) {
    uint4 u = *(const uint4*)wr;
    __half2 h0 = *(__half2*)&u.x, h1 = *(__half2*)&u.y;
    __half2 h2 = *(__half2*)&u.z, h3 = *(__half2*)&u.w;
    float2 f0 = __half22float2(h0), f1 = __half22float2(h1);
    float2 f2 = __half22float2(h2), f3 = __half22float2(h3);
    acc[0] += cf * f0.x; acc[1] += cf * f0.y;
    acc[2] += cf * f1.x; acc[3] += cf * f1.y;
    acc[4] += cf * f2.x; acc[5] += cf * f2.y;
    acc[6] += cf * f3.x; acc[7] += cf * f3.y;
}

__device__ __forceinline__ float sel8(const float v[8], int hq) {
    float a = (hq & 1) ? v[1] : v[0];
    float b = (hq & 1) ? v[3] : v[2];
    float c = (hq & 1) ? v[5] : v[4];
    float d = (hq & 1) ? v[7] : v[6];
    float ab = (hq & 2) ? b : a;
    float cd = (hq & 2) ? d : c;
    return (hq & 4) ? cd : ab;
}

// Single pass: M[h] = lrelu(asmax[h]+ad[h]) >= every edge logit (lrelu monotone),
// so softmax shift is safe and numerically bounded. No per-node max pass needed.
__device__ __forceinline__ void gat_relation(
    int lane, int warp, int hq, int beg, int cnt,
    const float* __restrict__ asb, const float* __restrict__ adp,
    const float* __restrict__ axp,
    const int* __restrict__ csr, const __half* __restrict__ Wh,
    float pbuf[8][32][H], int sbuf[8][32], float outacc[8])
{
    float ad[H], M[H];
    {
        float4 a0 = *(const float4*)adp;
        float4 a1 = *(const float4*)(adp + 4);
        float4 x0 = *(const float4*)axp;
        float4 x1 = *(const float4*)(axp + 4);
        ad[0]=a0.x; ad[1]=a0.y; ad[2]=a0.z; ad[3]=a0.w;
        ad[4]=a1.x; ad[5]=a1.y; ad[6]=a1.z; ad[7]=a1.w;
        M[0]=lrelu(x0.x+ad[0]); M[1]=lrelu(x0.y+ad[1]); M[2]=lrelu(x0.z+ad[2]); M[3]=lrelu(x0.w+ad[3]);
        M[4]=lrelu(x1.x+ad[4]); M[5]=lrelu(x1.y+ad[5]); M[6]=lrelu(x1.z+ad[6]); M[7]=lrelu(x1.w+ad[7]);
    }
    float lsum[H];
    #pragma unroll
    for (int h = 0; h < H; h++) lsum[h] = 0.f;
    float acc[8] = {};
    int nchunk = (cnt + 31) >> 5;
    for (int c = 0; c < nchunk; c++) {
        int e = c * 32 + lane;
        float p[H];
        int src = 0;
        if (e < cnt) {
            src = __ldg(&csr[beg + e]);
            float4 s0 = *(const float4*)(asb + (size_t)src * H);
            float4 s1 = *(const float4*)(asb + (size_t)src * H + 4);
            float ev[H];
            ev[0]=lrelu(s0.x+ad[0]); ev[1]=lrelu(s0.y+ad[1]); ev[2]=lrelu(s0.z+ad[2]); ev[3]=lrelu(s0.w+ad[3]);
            ev[4]=lrelu(s1.x+ad[4]); ev[5]=lrelu(s1.y+ad[5]); ev[6]=lrelu(s1.z+ad[6]); ev[7]=lrelu(s1.w+ad[7]);
            #pragma unroll
            for (int h = 0; h < H; h++) { p[h] = __expf(ev[h] - M[h]); lsum[h] += p[h]; }
        } else {
            #pragma unroll
            for (int h = 0; h < H; h++) p[h] = 0.f;
        }
        sbuf[warp][lane] = src;
        #pragma unroll
        for (int h = 0; h < H; h++) pbuf[warp][lane][h] = p[h];
        __syncwarp();
        int nv = min(32, cnt - c * 32);
        #pragma unroll 4
        for (int ee = 0; ee < nv; ee++) {
            int s2 = sbuf[warp][ee];
            float cf = pbuf[warp][ee][hq];
            acc_half8(acc, cf, Wh + (size_t)s2 * HD + lane * 8);
        }
        __syncwarp();
    }
    #pragma unroll
    for (int h = 0; h < H; h++)
        #pragma unroll
        for (int o = 16; o > 0; o >>= 1) lsum[h] += __shfl_xor_sync(0xffffffffu, lsum[h], o);
    float invs = 1.f / sel8(lsum, hq);
    #pragma unroll
    for (int j = 0; j < 8; j++) outacc[j] += acc[j] * invs;
}

__global__ void __launch_bounds__(256) k_gather_cc(float* __restrict__ out) {
    __shared__ float pbuf[8][32][H];
    __shared__ int   sbuf[8][32];
    int dt = blockIdx.y;
    int warp = threadIdx.x >> 5, lane = threadIdx.x & 31;
    int node = blockIdx.x * 8 + warp;
    if (node >= NC) return;
    int hq = lane >> 2;

    float outacc[8] = {};
    #pragma unroll 1
    for (int s = 0; s < 3; s++) {
        int r = 3 * s + dt;
        int beg = g_off_cc[r * NC + node];
        int cnt = g_cnt_cc[r * NC + node];
        if (cnt == 0) continue;
        gat_relation(lane, warp, hq, beg, cnt,
                     g_as_cc + (size_t)r * NC * H,
                     g_ad_cc + ((size_t)r * NC + node) * H,
                     g_asmax + r * H,
                     g_csr_cc + (size_t)r * ECC,
                     g_Wh_cc + (size_t)r * NC * HD,
                     pbuf, sbuf, outacc);
    }
    float* o = out + ((size_t)dt * NC + node) * HD + lane * 8;
    float4 v0, v1;
    v0.x = fmaxf(outacc[0], 0.f); v0.y = fmaxf(outacc[1], 0.f);
    v0.z = fmaxf(outacc[2], 0.f); v0.w = fmaxf(outacc[3], 0.f);
    v1.x = fmaxf(outacc[4], 0.f); v1.y = fmaxf(outacc[5], 0.f);
    v1.z = fmaxf(outacc[6], 0.f); v1.w = fmaxf(outacc[7], 0.f);
    *(float4*)o = v0; *(float4*)(o + 4) = v1;
}

__global__ void __launch_bounds__(256) k_gather_state(float* __restrict__ out) {
    __shared__ float pbuf[8][32][H];
    __shared__ int   sbuf[8][32];
    int warp = threadIdx.x >> 5, lane = threadIdx.x & 31;
    int node = blockIdx.x * 8 + warp;
    if (node >= NS) return;
    int hq = lane >> 2;

    float outacc[8] = {};
    acc_half8(outacc, 1.f, g_Wh_in + (size_t)node * HD + lane * 8);  // self term

    #pragma unroll 1
    for (int t = 0; t < 3; t++) {
        int beg = g_off_cs[t * NS + node];
        int cnt = g_cnt_cs[t * NS + node];
        if (cnt == 0) continue;
        gat_relation(lane, warp, hq, beg, cnt,
                     g_as_cs + (size_t)t * NC * H,
                     g_ad_s + ((size_t)t * NS + node) * H,
                     g_asmax + (9 + t) * H,
                     g_csr_cs + (size_t)t * ECS,
                     g_Wh_cs + (size_t)t * NC * HD,
                     pbuf, sbuf, outacc);
    }
    float* o = out + (size_t)3 * NC * HD + (size_t)node * HD + lane * 8;
    float4 v0, v1;
    v0.x = fmaxf(outacc[0], 0.f); v0.y = fmaxf(outacc[1], 0.f);
    v0.z = fmaxf(outacc[2], 0.f); v0.w = fmaxf(outacc[3], 0.f);
    v1.x = fmaxf(outacc[4], 0.f); v1.y = fmaxf(outacc[5], 0.f);
    v1.z = fmaxf(outacc[6], 0.f); v1.w = fmaxf(outacc[7], 0.f);
    *(float4*)o = v0; *(float4*)(o + 4) = v1;
}

// ---------------- launch: fork/join two independent chains ----------------
static cudaStream_t g_s1 = 0;
static cudaEvent_t g_evFork = 0, g_evCsr = 0, g_evComp = 0, g_evState = 0;

extern "C" void kernel_launch(void* const* d_in, const int* in_sizes, int n_in,
                              void* d_out, int out_size) {
    const float* f1      = (const float*)d_in[0];
    const float* f2      = (const float*)d_in[1];
    const float* f3      = (const float*)d_in[2];
    const float* fs      = (const float*)d_in[3];
    const float* W_node  = (const float*)d_in[4];
    const float* b_node  = (const float*)d_in[5];
    const float* W_cc    = (const float*)d_in[6];
    const float* b_cc    = (const float*)d_in[7];
    const float* W_cs    = (const float*)d_in[8];
    const float* b_cs    = (const float*)d_in[9];
    const float* W_in    = (const float*)d_in[10];
    const float* b_in    = (const float*)d_in[11];
    const float* attn_cc = (const float*)d_in[12];
    const float* attn_cs = (const float*)d_in[13];
    const int* ecc_src   = (const int*)d_in[14];
    const int* ecc_dst   = (const int*)d_in[15];
    const int* ecs_src   = (const int*)d_in[16];
    const int* ecs_dst   = (const int*)d_in[17];
    float* out = (float*)d_out;

    if (!g_s1) {   // lazy init on first (uncaptured) call; no device memory allocated
        cudaStreamCreateWithFlags(&g_s1, cudaStreamNonBlocking);
        cudaEventCreateWithFlags(&g_evFork, cudaEventDisableTiming);
        cudaEventCreateWithFlags(&g_evCsr, cudaEventDisableTiming);
        cudaEventCreateWithFlags(&g_evComp, cudaEventDisableTiming);
        cudaEventCreateWithFlags(&g_evState, cudaEventDisableTiming);
    }

    int tot = 9 * ECC + 3 * ECS;

    // fork: CSR chain on s1 (depends only on edge lists)
    cudaEventRecord(g_evFork, 0);
    cudaStreamWaitEvent(g_s1, g_evFork, 0);
    k_zero_counters<<<(9 * NC + 255) / 256, 256, 0, g_s1>>>();
    k_hist<<<(tot + 255) / 256, 256, 0, g_s1>>>(ecc_dst, ecs_dst);
    k_scan<<<12, 1024, 0, g_s1>>>();
    k_scatter<<<(tot + 255) / 256, 256, 0, g_s1>>>(ecc_src, ecc_dst, ecs_src, ecs_dst);
    cudaEventRecord(g_evCsr, g_s1);

    // main stream: projection chain
    k_wred<<<(24 * INC * H + 255) / 256, 256>>>(W_node, b_node, W_cc, b_cc, W_cs, b_cs, W_in, b_in, attn_cc, attn_cs);
    k_skinny<<<dim3(1250, 4), 256>>>(f1, f2, f3, fs);
    k_asmax<<<12, 256>>>();
    k_gemm<<<dim3(79, 2, 13), 256>>>(f1, f2, f3, fs, W_cc, b_cc, W_cs, b_cs, W_in, b_in);
    cudaEventRecord(g_evComp, 0);

    // state gather on s1 (after CSR chain, stream-ordered; + compute)
    cudaStreamWaitEvent(g_s1, g_evComp, 0);
    k_gather_state<<<128, 256, 0, g_s1>>>(out);
    cudaEventRecord(g_evState, g_s1);

    // cc gather on main stream (after compute, stream-ordered; + CSR)
    cudaStreamWaitEvent(0, g_evCsr, 0);
    k_gather_cc<<<dim3(1250, 3), 256>>>(out);

    // join state branch back
    cudaStreamWaitEvent(0, g_evState, 0);
}